// round 14
// baseline (speedup 1.0000x reference)
#include <cuda_runtime.h>
#include <cuda_fp16.h>
#include <mma.h>
#include <cstdint>

using namespace nvcuda;

#define FULLMASK 0xffffffffu
#define B2   2
#define CDIM 256
#define NQ   1024
#define NKW  1344
#define TOPK 16
#define NWIN 2048          // B2*NQ
#define MROWS (NWIN*64)    // 131072

// pipelined GEMM geometry (v5: 4 warps, 64x64 warp tiles, BK=64, 2 stages)
#define BM 128
#define BN 128
#define BK 64
#define NKIT (CDIM / BK)   // 4
#define LDT 72             // padded half stride per stage row
#define STAGE_HALFS (256 * LDT)             // A(128 rows)+B(128 rows)
#define SMEM_GEMM (2 * STAGE_HALFS * 2)     // 73728 bytes

// sim pipeline geometry
#define SLD 20             // padded float stride (16 data + 4 pad)
#define SIM_STAGE_F (2 * 64 * SLD)          // A+B rows per stage (floats)

// ---------------- device scratch ----------------
__device__ float  g_qg [B2*NQ*CDIM];
__device__ float  g_sim[B2*NQ*NKW];
__device__ int    g_top[B2*NQ*TOPK];
__device__ int    g_idx[B2*NQ];
__device__ __half g_Wq[CDIM*CDIM], g_Wkv[2*CDIM*CDIM], g_Wp[CDIM*CDIM];
__device__ __half g_qwh[(size_t)MROWS*CDIM];
__device__ __half g_kwh[(size_t)MROWS*CDIM];
__device__ __half g_qh [(size_t)MROWS*CDIM];
__device__ __half g_kh [(size_t)MROWS*CDIM];
__device__ __half g_vh [(size_t)MROWS*CDIM];
__device__ float  g_x  [(size_t)MROWS*CDIM];
__device__ __half g_ln [(size_t)MROWS*CDIM];
__device__ float  g_bias[8*64*64];

// ---------------- cp.async helpers ----------------
__device__ __forceinline__ void cpa16(unsigned saddr, const void* gaddr) {
    asm volatile("cp.async.cg.shared.global [%0], [%1], 16;" :: "r"(saddr), "l"(gaddr));
}
__device__ __forceinline__ void cpa_commit() {
    asm volatile("cp.async.commit_group;");
}
__device__ __forceinline__ void cpa_wait0() {
    asm volatile("cp.async.wait_group 0;" ::: "memory");
}

// ---------------- prep kernels ----------------
__global__ void conv_w_kernel(const float* __restrict__ Wq, const float* __restrict__ Wk,
                              const float* __restrict__ Wv, const float* __restrict__ Wp) {
    int i = blockIdx.x * 256 + threadIdx.x;   // 4*65536
    int j = i & 65535;
    switch (i >> 16) {
        case 0: g_Wq[j] = __float2half(Wq[j]); break;
        case 1: g_Wkv[j] = __float2half(Wk[j]); break;              // rows 0..255
        case 2: g_Wkv[65536 + j] = __float2half(Wv[j]); break;      // rows 256..511
        default: g_Wp[j] = __float2half(Wp[j]); break;
    }
}

__global__ void bias_kernel(const float* __restrict__ table) {
    int e = blockIdx.x * 256 + threadIdx.x;   // 32768
    int h = e >> 12, n = (e >> 6) & 63, m = e & 63;
    int rp = ((n >> 3) - (m >> 3) + 7) * 15 + ((n & 7) - (m & 7) + 7);
    g_bias[e] = table[rp * 8 + h];
}

// fused: window-partition q -> half, and window-mean -> g_qg (single q read)
__global__ void __launch_bounds__(256) pack_qg_kernel(const float* __restrict__ q) {
    int w = blockIdx.x;                        // 0..2047
    int c = threadIdx.x;
    int b = w >> 10, hg = (w >> 5) & 31, wg = w & 31;
    const float* base = q + (((size_t)(b * 256 + hg * 8)) * 256 + wg * 8) * 256 + c;
    __half* dst = g_qwh + (size_t)w * 64 * 256 + c;
    float s = 0.f;
#pragma unroll
    for (int i = 0; i < 8; i++)
#pragma unroll
        for (int j = 0; j < 8; j++) {
            float v = base[(size_t)(i * 256 + j) * 256];
            s += v;
            dst[(size_t)(i * 8 + j) * 256] = __float2half(v);
        }
    g_qg[(size_t)w * 256 + c] = s * (1.0f / 64.0f);
}

// ---------------- sim = qg @ kg^T (fp32, cp.async 2-stage) ----------------
__global__ void __launch_bounds__(256) sim_kernel(const float* __restrict__ kg1,
                                                  const float* __restrict__ kg2,
                                                  const float* __restrict__ kg3) {
    __shared__ float buf[2][SIM_STAGE_F];
    __shared__ const float* browp[64];
    int b = blockIdx.z;
    int r0 = blockIdx.y * 64;
    int c0 = blockIdx.x * 64;
    int t = threadIdx.x;
    int ty = t >> 4, tx = t & 15;

    if (t < 64) {
        int m = c0 + t;
        const float* p;
        if (m < 1024)      p = kg1 + (size_t)(b * 1024 + m) * 256;
        else if (m < 1280) p = kg2 + (size_t)(b * 256 + m - 1024) * 256;
        else               p = kg3 + (size_t)(b * 64  + m - 1280) * 256;
        browp[t] = p;
    }
    __syncthreads();

    const float* abase = g_qg + (size_t)(b * NQ + r0) * 256;
    unsigned smem_u32 = (unsigned)__cvta_generic_to_shared(&buf[0][0]);

    auto load_stage = [&](int st, int kit) {
        int k0 = kit * 16;
        unsigned sb = smem_u32 + (unsigned)(st * SIM_STAGE_F) * 4u;
#pragma unroll
        for (int u = 0; u < 2; u++) {
            int c = t + u * 256;          // 0..511
            int reg = c >> 8;             // 0=A, 1=B
            int rc = c & 255;
            int row = rc >> 2, seg = (rc & 3) << 2;
            const float* g = (reg == 0) ? (abase + (size_t)row * 256 + k0 + seg)
                                        : (browp[row] + k0 + seg);
            unsigned dst = sb + (unsigned)((reg * 64 + row) * SLD + seg) * 4u;
            cpa16(dst, g);
        }
        cpa_commit();
    };

    float acc[4][4];
#pragma unroll
    for (int i = 0; i < 4; i++)
#pragma unroll
        for (int j = 0; j < 4; j++) acc[i][j] = 0.f;

    load_stage(0, 0);
#pragma unroll
    for (int k = 0; k < 16; k++) {
        cpa_wait0();
        __syncthreads();
        if (k + 1 < 16) load_stage((k + 1) & 1, k + 1);
        const float* As = buf[k & 1];
        const float* Bs = As + 64 * SLD;
#pragma unroll
        for (int kk = 0; kk < 16; kk++) {
            float a_[4], b_[4];
#pragma unroll
            for (int i = 0; i < 4; i++) a_[i] = As[(ty * 4 + i) * SLD + kk];
#pragma unroll
            for (int j = 0; j < 4; j++) b_[j] = Bs[(tx * 4 + j) * SLD + kk];
#pragma unroll
            for (int i = 0; i < 4; i++)
#pragma unroll
                for (int j = 0; j < 4; j++) acc[i][j] += a_[i] * b_[j];
        }
    }
#pragma unroll
    for (int i = 0; i < 4; i++)
#pragma unroll
        for (int j = 0; j < 4; j++)
            g_sim[(size_t)(b * NQ + r0 + ty * 4 + i) * NKW + c0 + tx * 4 + j] = acc[i][j];
}

// ---------------- top-16 per row: one warp per row, register-resident ----------------
__global__ void __launch_bounds__(128) topk_kernel() {
    int r = blockIdx.x * 4 + (threadIdx.x >> 5);   // 4 rows per block
    int lane = threadIdx.x & 31;
    const float* row = g_sim + (size_t)r * NKW;
    float v[42];
#pragma unroll
    for (int i = 0; i < 42; i++) v[i] = row[i * 32 + lane];
    unsigned long long used = 0ull;
    for (int it = 0; it < TOPK; it++) {
        float bv = -1e38f; int bidx = 0;
#pragma unroll
        for (int i = 0; i < 42; i++) {
            bool ok = !((used >> i) & 1ull);
            if (ok && v[i] > bv) { bv = v[i]; bidx = i; }
        }
        int gi = bidx * 32 + lane;
#pragma unroll
        for (int off = 16; off; off >>= 1) {
            float ov = __shfl_down_sync(FULLMASK, bv, off);
            int   oi = __shfl_down_sync(FULLMASK, gi, off);
            if (ov > bv || (ov == bv && oi < gi)) { bv = ov; gi = oi; }
        }
        gi = __shfl_sync(FULLMASK, gi, 0);
        if (lane == 0) g_top[r * TOPK + it] = gi;
        if ((gi & 31) == lane) used |= 1ull << (gi >> 5);
    }
}

// ---------------- greedy assignment (1 warp per batch, pipelined candidate fetch) ----------------
__global__ void greedy_kernel() {
    int b = blockIdx.x;
    int lane = threadIdx.x;
    __shared__ unsigned short tops[NQ * TOPK];
    __shared__ unsigned used[42];
    for (int i = lane; i < NQ * TOPK; i += 32) tops[i] = (unsigned short)g_top[b * NQ * TOPK + i];
    for (int i = lane; i < 42; i += 32) used[i] = 0u;
    __syncwarp();

    int cand = (lane < TOPK) ? (int)tops[lane] : 0;   // prefetch row 0
    for (int n = 0; n < NQ; n++) {
        int ncand = (lane < TOPK && n + 1 < NQ) ? (int)tops[(n + 1) * TOPK + lane] : 0;
        bool fr = (lane < TOPK) && !((used[cand >> 5] >> (cand & 31)) & 1);
        unsigned bal = __ballot_sync(FULLMASK, fr);
        int chosen;
        if (bal) {
            int j = __ffs(bal) - 1;
            chosen = __shfl_sync(FULLMASK, cand, j);
        } else {
            const float* row = g_sim + ((size_t)b * NQ + n) * NKW;
            float bv = -1e38f; int bi = NKW;
            for (int m = lane; m < NKW; m += 32) {
                if (!((used[m >> 5] >> (m & 31)) & 1)) {
                    float vv = row[m];
                    if (vv > bv) { bv = vv; bi = m; }
                }
            }
#pragma unroll
            for (int off = 16; off; off >>= 1) {
                float ov = __shfl_down_sync(FULLMASK, bv, off);
                int   oi = __shfl_down_sync(FULLMASK, bi, off);
                if (ov > bv || (ov == bv && oi < bi)) { bv = ov; bi = oi; }
            }
            chosen = __shfl_sync(FULLMASK, bi, 0);
        }
        if (lane == 0) {
            used[chosen >> 5] |= 1u << (chosen & 31);
            g_idx[b * NQ + n] = chosen;
        }
        __syncwarp();
        cand = ncand;
    }
}

// ---------------- gather assigned k windows -> half (float4 per thread) ----------------
__global__ void __launch_bounds__(256) pack_k_kernel(const float* __restrict__ k1,
                                                     const float* __restrict__ k2,
                                                     const float* __restrict__ k3) {
    size_t gid = (size_t)blockIdx.x * 256 + threadIdx.x;  // each handles 4 elems
    int c = (int)(gid & 63) << 2;
    int rest = (int)(gid >> 6);
    int n = rest & 63, w = rest >> 6;
    int b = w >> 10;
    int win = g_idx[w];
    const float* src;
    if (win < 1024)      src = k1 + ((size_t)(b * 1024 + win) * 64 + n) * 256 + c;
    else if (win < 1280) src = k2 + ((size_t)(b * 256 + win - 1024) * 64 + n) * 256 + c;
    else                 src = k3 + ((size_t)(b * 64 + win - 1280) * 64 + n) * 256 + c;
    float4 v = *(const float4*)src;
    __half h[4] = {__float2half(v.x), __float2half(v.y), __float2half(v.z), __float2half(v.w)};
    *(float2*)(g_kwh + gid * 4) = *(float2*)h;
}

// ---------------- GEMM v5: 4 warps, 64x64 warp tiles, cp.async 2-stage ----------------
// MODE 0: half out = (acc+bias)*scale   MODE 1: half out = acc+bias (dual-output capable)
// MODE 2: float out = resid + acc + bias
// Dual output (MODE 1 + bias2): blocks with n0>=256 write (out2, bias2) at col n-256.
template<int MODE>
__global__ void __launch_bounds__(128, 2) gemm5_kernel(const __half* __restrict__ A,
                                                       const __half* __restrict__ W,
                                                       const float* __restrict__ bias,
                                                       const float* __restrict__ bias2,
                                                       const float* __restrict__ resid,
                                                       void* __restrict__ out,
                                                       void* __restrict__ out2,
                                                       float scale) {
    extern __shared__ __half sm[];
    int t = threadIdx.x;
    int wid = t >> 5, lane = t & 31;
    int wm = wid >> 1, wn = wid & 1;                    // 2x2 warps, each 64x64
    int m0 = blockIdx.y * BM;
    int n0 = blockIdx.x * BN;
    unsigned smem_u32 = (unsigned)__cvta_generic_to_shared(sm);

    const __half* Ag = A + (size_t)m0 * 256;
    const __half* Wg = W + (size_t)n0 * 256;

    auto load_stage = [&](int st, int kit) {
        int k0 = kit * BK;
        unsigned sa = smem_u32 + (unsigned)(st * STAGE_HALFS) * 2u;
        unsigned sb = sa + (unsigned)(128 * LDT) * 2u;
#pragma unroll
        for (int u = 0; u < 8; u++) {
            int c = t + u * 128;                        // 0..1023
            int row = c >> 3, seg = (c & 7) << 3;       // seg in halfs
            cpa16(sa + (unsigned)(row * LDT + seg) * 2u, Ag + (size_t)row * 256 + k0 + seg);
            cpa16(sb + (unsigned)(row * LDT + seg) * 2u, Wg + (size_t)row * 256 + k0 + seg);
        }
        cpa_commit();
    };

    wmma::fragment<wmma::accumulator, 16, 16, 16, float> acc[4][4];
#pragma unroll
    for (int i = 0; i < 4; i++)
#pragma unroll
        for (int j = 0; j < 4; j++) wmma::fill_fragment(acc[i][j], 0.f);

    load_stage(0, 0);
#pragma unroll
    for (int k = 0; k < NKIT; k++) {
        cpa_wait0();
        __syncthreads();
        if (k + 1 < NKIT) load_stage((k + 1) & 1, k + 1);

        const __half* As = sm + (size_t)(k & 1) * STAGE_HALFS;
        const __half* Bs = As + 128 * LDT;
#pragma unroll
        for (int kk = 0; kk < BK; kk += 16) {
            wmma::fragment<wmma::matrix_a, 16, 16, 16, __half, wmma::row_major> a[4];
#pragma unroll
            for (int i = 0; i < 4; i++)
                wmma::load_matrix_sync(a[i], As + (wm * 64 + i * 16) * LDT + kk, LDT);
#pragma unroll
            for (int j = 0; j < 4; j++) {
                wmma::fragment<wmma::matrix_b, 16, 16, 16, __half, wmma::col_major> b;
                wmma::load_matrix_sync(b, Bs + (wn * 64 + j * 16) * LDT + kk, LDT);
#pragma unroll
                for (int i = 0; i < 4; i++)
                    wmma::mma_sync(acc[i][j], a[i], b, acc[i][j]);
            }
        }
    }
    __syncthreads();   // stages now dead -> reuse for epilogue staging

    // dual-output selection (K/V fused projection)
    const float* biasE = bias;
    void* outE = out;
    int nsub = 0;
    if (MODE == 1 && bias2 != nullptr && n0 >= 256) { biasE = bias2; outE = out2; nsub = 256; }

    float* wstg = (float*)sm + wid * 320;               // 16x20 floats per warp
    int r = lane >> 1, cs = (lane & 1) << 3;
#pragma unroll
    for (int i = 0; i < 4; i++)
#pragma unroll
        for (int j = 0; j < 4; j++) {
            wmma::store_matrix_sync(wstg, acc[i][j], 20, wmma::mem_row_major);
            __syncwarp();
            int m = m0 + wm * 64 + i * 16 + r;
            int n = n0 + wn * 64 + j * 16 + cs;
            int nc = n - nsub;
            size_t off = (size_t)m * 256 + nc;
            float v[8];
#pragma unroll
            for (int c = 0; c < 8; c++) v[c] = wstg[r * 20 + cs + c] + biasE[nc + c];
            if (MODE == 2) {
                float4 r0 = *(const float4*)(resid + off);
                float4 r1 = *(const float4*)(resid + off + 4);
                float4 w0 = {r0.x + v[0], r0.y + v[1], r0.z + v[2], r0.w + v[3]};
                float4 w1 = {r1.x + v[4], r1.y + v[5], r1.z + v[6], r1.w + v[7]};
                float* op = (float*)outE + off;
                *(float4*)op = w0; *(float4*)(op + 4) = w1;
            } else {
                __half h[8];
#pragma unroll
                for (int c = 0; c < 8; c++)
                    h[c] = __float2half(MODE == 0 ? v[c] * scale : v[c]);
                *(float4*)((__half*)outE + off) = *(float4*)h;
            }
            __syncwarp();
        }
}

// ---------------- attention per (window, head), smem-staged ----------------
__global__ void __launch_bounds__(256) attn_kernel(const float* __restrict__ qin) {
    __shared__ __half qs[64 * 40], ks[64 * 40], vs[64 * 40];
    __shared__ float  Ssm[64 * 68];
    __shared__ __half Psm[64 * 72];

    int w = blockIdx.x >> 3;
    int head = blockIdx.x & 7;
    int t = threadIdx.x;
    int wid = t >> 5;

    const __half* qb = g_qh + (size_t)w * 64 * 256 + head * 32;
    const __half* kb = g_kh + (size_t)w * 64 * 256 + head * 32;
    const __half* vb = g_vh + (size_t)w * 64 * 256 + head * 32;

    {
        int row = t >> 2, seg = (t & 3) << 3;
        *(float4*)(qs + row * 40 + seg) = *(const float4*)(qb + (size_t)row * 256 + seg);
        *(float4*)(ks + row * 40 + seg) = *(const float4*)(kb + (size_t)row * 256 + seg);
        *(float4*)(vs + row * 40 + seg) = *(const float4*)(vb + (size_t)row * 256 + seg);
    }
    __syncthreads();

#pragma unroll
    for (int tt = 0; tt < 2; tt++) {
        int tile = wid + tt * 8;
        int tr = tile >> 2, tc = tile & 3;
        wmma::fragment<wmma::accumulator, 16, 16, 16, float> acc;
        wmma::fill_fragment(acc, 0.f);
#pragma unroll
        for (int kk = 0; kk < 32; kk += 16) {
            wmma::fragment<wmma::matrix_a, 16, 16, 16, __half, wmma::row_major> a;
            wmma::fragment<wmma::matrix_b, 16, 16, 16, __half, wmma::col_major> b;
            wmma::load_matrix_sync(a, qs + (tr * 16) * 40 + kk, 40);
            wmma::load_matrix_sync(b, ks + (tc * 16) * 40 + kk, 40);
            wmma::mma_sync(acc, a, b, acc);
        }
        wmma::store_matrix_sync(Ssm + tr * 16 * 68 + tc * 16, acc, 68, wmma::mem_row_major);
    }
    __syncthreads();

    {
        int r = t >> 2, sub = t & 3;
        const float* brow = g_bias + head * 4096 + r * 64 + sub * 16;
        float vals[16];
        float mx = -1e38f;
#pragma unroll
        for (int i = 0; i < 16; i++) {
            vals[i] = Ssm[r * 68 + sub * 16 + i] + brow[i];
            mx = fmaxf(mx, vals[i]);
        }
        mx = fmaxf(mx, __shfl_xor_sync(FULLMASK, mx, 1));
        mx = fmaxf(mx, __shfl_xor_sync(FULLMASK, mx, 2));
        float sum = 0.f;
#pragma unroll
        for (int i = 0; i < 16; i++) {
            vals[i] = __expf(vals[i] - mx);
            sum += vals[i];
        }
        sum += __shfl_xor_sync(FULLMASK, sum, 1);
        sum += __shfl_xor_sync(FULLMASK, sum, 2);
        float inv = 1.0f / sum;
#pragma unroll
        for (int i = 0; i < 16; i++)
            Psm[r * 72 + sub * 16 + i] = __float2half(vals[i] * inv);
    }
    __syncthreads();

    {
        int tr = wid >> 1, tc = wid & 1;
        wmma::fragment<wmma::accumulator, 16, 16, 16, float> acc;
        wmma::fill_fragment(acc, 0.f);
#pragma unroll
        for (int mm = 0; mm < 64; mm += 16) {
            wmma::fragment<wmma::matrix_a, 16, 16, 16, __half, wmma::row_major> a;
            wmma::fragment<wmma::matrix_b, 16, 16, 16, __half, wmma::row_major> b;
            wmma::load_matrix_sync(a, Psm + tr * 16 * 72 + mm, 72);
            wmma::load_matrix_sync(b, vs + mm * 40 + tc * 16, 40);
            wmma::mma_sync(acc, a, b, acc);
        }
        wmma::store_matrix_sync(Ssm + tr * 16 * 36 + tc * 16, acc, 36, wmma::mem_row_major);
    }
    __syncthreads();

    {
        int b = w >> 10, hg = (w >> 5) & 31, wg = w & 31;
#pragma unroll
        for (int e0 = 0; e0 < 8; e0++) {
            int e = t * 8 + e0;
            int n = e >> 5, d = e & 31;
            int i = n >> 3, j = n & 7;
            size_t pix = (size_t)(b * 256 + hg * 8 + i) * 256 + wg * 8 + j;
            size_t off = pix * 256 + head * 32 + d;
            g_x[off] = qin[off] + Ssm[n * 36 + d];
        }
    }
}

// ---------------- LayerNorm -> half ----------------
__global__ void __launch_bounds__(256) ln_kernel(const float* __restrict__ lg,
                                                 const float* __restrict__ lb) {
    int row = blockIdx.x * 8 + (threadIdx.x >> 5);
    int lane = threadIdx.x & 31;
    const float* xr = g_x + (size_t)row * 256;
    float4 v0 = *(const float4*)(xr + lane * 8);
    float4 v1 = *(const float4*)(xr + lane * 8 + 4);
    float s = v0.x + v0.y + v0.z + v0.w + v1.x + v1.y + v1.z + v1.w;
#pragma unroll
    for (int off = 16; off; off >>= 1) s += __shfl_xor_sync(FULLMASK, s, off);
    float mu = s * (1.0f / 256.0f);
    float vs = 0.f;
    float d0[8] = {v0.x - mu, v0.y - mu, v0.z - mu, v0.w - mu,
                   v1.x - mu, v1.y - mu, v1.z - mu, v1.w - mu};
#pragma unroll
    for (int i = 0; i < 8; i++) vs += d0[i] * d0[i];
#pragma unroll
    for (int off = 16; off; off >>= 1) vs += __shfl_xor_sync(FULLMASK, vs, off);
    float rstd = rsqrtf(vs * (1.0f / 256.0f) + 1e-5f);
    __half* o = g_ln + (size_t)row * 256 + lane * 8;
#pragma unroll
    for (int i = 0; i < 8; i++) {
        int c = lane * 8 + i;
        o[i] = __float2half(d0[i] * rstd * lg[c] + lb[c]);
    }
}

// ---------------- launch ----------------
extern "C" void kernel_launch(void* const* d_in, const int* in_sizes, int n_in,
                              void* d_out, int out_size) {
    const float* q   = (const float*)d_in[0];
    const float* k1  = (const float*)d_in[1];
    const float* k2  = (const float*)d_in[2];
    const float* k3  = (const float*)d_in[3];
    const float* kg1 = (const float*)d_in[4];
    const float* kg2 = (const float*)d_in[5];
    const float* kg3 = (const float*)d_in[6];
    const float* rbt = (const float*)d_in[7];
    const float* Wq  = (const float*)d_in[8];
    const float* bq  = (const float*)d_in[9];
    const float* Wk  = (const float*)d_in[10];
    const float* bk  = (const float*)d_in[11];
    const float* Wv  = (const float*)d_in[12];
    const float* bv  = (const float*)d_in[13];
    const float* lng = (const float*)d_in[14];
    const float* lnb = (const float*)d_in[15];
    const float* Wp  = (const float*)d_in[16];
    const float* bp  = (const float*)d_in[17];
    float* out = (float*)d_out;

    __half *dWq, *dWkv, *dWp, *dqwh, *dkwh, *dqh, *dkh, *dvh, *dln;
    float *dx;
    cudaGetSymbolAddress((void**)&dWq,  g_Wq);
    cudaGetSymbolAddress((void**)&dWkv, g_Wkv);
    cudaGetSymbolAddress((void**)&dWp,  g_Wp);
    cudaGetSymbolAddress((void**)&dqwh, g_qwh);
    cudaGetSymbolAddress((void**)&dkwh, g_kwh);
    cudaGetSymbolAddress((void**)&dqh,  g_qh);
    cudaGetSymbolAddress((void**)&dkh,  g_kh);
    cudaGetSymbolAddress((void**)&dvh,  g_vh);
    cudaGetSymbolAddress((void**)&dln,  g_ln);
    cudaGetSymbolAddress((void**)&dx,   g_x);

    cudaFuncSetAttribute(gemm5_kernel<0>, cudaFuncAttributeMaxDynamicSharedMemorySize, SMEM_GEMM);
    cudaFuncSetAttribute(gemm5_kernel<1>, cudaFuncAttributeMaxDynamicSharedMemorySize, SMEM_GEMM);
    cudaFuncSetAttribute(gemm5_kernel<2>, cudaFuncAttributeMaxDynamicSharedMemorySize, SMEM_GEMM);

    const float scale = 0.17677669529663687f;   // 32^-0.5

    // fork-join, corrected placement: the latency-bound greedy chain overlaps
    // the throughput-bound q-projection (no SM contention). One stream + two
    // events — the exact resource set that passed the teardown memory check
    // in rounds 8 and 11.
    cudaStream_t s2;
    cudaEvent_t e1, e2;
    cudaStreamCreateWithFlags(&s2, cudaStreamNonBlocking);
    cudaEventCreateWithFlags(&e1, cudaEventDisableTiming);
    cudaEventCreateWithFlags(&e2, cudaEventDisableTiming);

    pack_qg_kernel<<<NWIN, 256>>>(q);                              // 1
    sim_kernel<<<dim3(21, 16, 2), 256>>>(kg1, kg2, kg3);           // 2
    topk_kernel<<<NWIN / 4, 128>>>();                              // 3
    cudaEventRecord(e1, 0);

    cudaStreamWaitEvent(s2, e1, 0);
    greedy_kernel<<<2, 32, 0, s2>>>();                             // 4 <- ncu capture slot
    pack_k_kernel<<<MROWS * 64 / 256, 256, 0, s2>>>(k1, k2, k3);   // 5
    cudaEventRecord(e2, s2);

    // main stream: weight conversion + q-projection run under the greedy chain
    conv_w_kernel<<<1024, 256>>>(Wq, Wk, Wv, Wp);                  // 6
    bias_kernel<<<128, 256>>>(rbt);                                // 7
    gemm5_kernel<0><<<dim3(2, 1024), 128, SMEM_GEMM>>>(dqwh, dWq, bq, nullptr, nullptr,
                                                       dqh, nullptr, scale);   // 8

    cudaStreamWaitEvent(0, e2, 0);
    // fused K+V projection: W stacked [512,256], grid.x=4 covers both outputs
    gemm5_kernel<1><<<dim3(4, 1024), 128, SMEM_GEMM>>>(dkwh, dWkv, bk, bv, nullptr,
                                                       dkh, dvh, 0.f);

    attn_kernel<<<NWIN * 8, 256>>>(q);
    ln_kernel<<<MROWS / 8, 256>>>(lng, lnb);
    gemm5_kernel<2><<<dim3(2, 1024), 128, SMEM_GEMM>>>(dln, dWp, bp, nullptr, dx,
                                                       out, nullptr, 0.f);
}

// round 15
// speedup vs baseline: 1.0284x; 1.0284x over previous
#include <cuda_runtime.h>
#include <cuda_fp16.h>
#include <mma.h>
#include <cstdint>

using namespace nvcuda;

#define FULLMASK 0xffffffffu
#define B2   2
#define CDIM 256
#define NQ   1024
#define NKW  1344
#define TOPK 32
#define NWIN 2048          // B2*NQ
#define MROWS (NWIN*64)    // 131072

// pipelined GEMM geometry (v5: 4 warps, 64x64 warp tiles, BK=64, 2 stages)
#define BM 128
#define BN 128
#define BK 64
#define NKIT (CDIM / BK)   // 4
#define LDT 72             // padded half stride per stage row
#define STAGE_HALFS (256 * LDT)             // A(128 rows)+B(128 rows)
#define SMEM_GEMM (2 * STAGE_HALFS * 2)     // 73728 bytes
#define SMEM_GREEDY (NQ * TOPK * 2)         // 65536 bytes (dynamic)

// sim pipeline geometry
#define SLD 20             // padded float stride (16 data + 4 pad)
#define SIM_STAGE_F (2 * 64 * SLD)          // A+B rows per stage (floats)

// ---------------- device scratch ----------------
__device__ float  g_qg [B2*NQ*CDIM];
__device__ float  g_sim[B2*NQ*NKW];
__device__ int    g_top[B2*NQ*TOPK];
__device__ int    g_idx[B2*NQ];
__device__ __half g_Wq[CDIM*CDIM], g_Wkv[2*CDIM*CDIM], g_Wp[CDIM*CDIM];
__device__ __half g_qwh[(size_t)MROWS*CDIM];
__device__ __half g_kwh[(size_t)MROWS*CDIM];
__device__ __half g_qh [(size_t)MROWS*CDIM];
__device__ __half g_kh [(size_t)MROWS*CDIM];
__device__ __half g_vh [(size_t)MROWS*CDIM];
__device__ float  g_x  [(size_t)MROWS*CDIM];
__device__ __half g_ln [(size_t)MROWS*CDIM];
__device__ float  g_bias[8*64*64];

// ---------------- cp.async helpers ----------------
__device__ __forceinline__ void cpa16(unsigned saddr, const void* gaddr) {
    asm volatile("cp.async.cg.shared.global [%0], [%1], 16;" :: "r"(saddr), "l"(gaddr));
}
__device__ __forceinline__ void cpa_commit() {
    asm volatile("cp.async.commit_group;");
}
__device__ __forceinline__ void cpa_wait0() {
    asm volatile("cp.async.wait_group 0;" ::: "memory");
}

// ---------------- prep kernels ----------------
__global__ void conv_w_kernel(const float* __restrict__ Wq, const float* __restrict__ Wk,
                              const float* __restrict__ Wv, const float* __restrict__ Wp) {
    int i = blockIdx.x * 256 + threadIdx.x;   // 4*65536
    int j = i & 65535;
    switch (i >> 16) {
        case 0: g_Wq[j] = __float2half(Wq[j]); break;
        case 1: g_Wkv[j] = __float2half(Wk[j]); break;              // rows 0..255
        case 2: g_Wkv[65536 + j] = __float2half(Wv[j]); break;      // rows 256..511
        default: g_Wp[j] = __float2half(Wp[j]); break;
    }
}

__global__ void bias_kernel(const float* __restrict__ table) {
    int e = blockIdx.x * 256 + threadIdx.x;   // 32768
    int h = e >> 12, n = (e >> 6) & 63, m = e & 63;
    int rp = ((n >> 3) - (m >> 3) + 7) * 15 + ((n & 7) - (m & 7) + 7);
    g_bias[e] = table[rp * 8 + h];
}

// fused: window-partition q -> half, and window-mean -> g_qg (single q read)
__global__ void __launch_bounds__(256) pack_qg_kernel(const float* __restrict__ q) {
    int w = blockIdx.x;                        // 0..2047
    int c = threadIdx.x;
    int b = w >> 10, hg = (w >> 5) & 31, wg = w & 31;
    const float* base = q + (((size_t)(b * 256 + hg * 8)) * 256 + wg * 8) * 256 + c;
    __half* dst = g_qwh + (size_t)w * 64 * 256 + c;
    float s = 0.f;
#pragma unroll
    for (int i = 0; i < 8; i++)
#pragma unroll
        for (int j = 0; j < 8; j++) {
            float v = base[(size_t)(i * 256 + j) * 256];
            s += v;
            dst[(size_t)(i * 8 + j) * 256] = __float2half(v);
        }
    g_qg[(size_t)w * 256 + c] = s * (1.0f / 64.0f);
}

// ---------------- sim = qg @ kg^T (fp32, cp.async 2-stage) ----------------
__global__ void __launch_bounds__(256) sim_kernel(const float* __restrict__ kg1,
                                                  const float* __restrict__ kg2,
                                                  const float* __restrict__ kg3) {
    __shared__ float buf[2][SIM_STAGE_F];
    __shared__ const float* browp[64];
    int b = blockIdx.z;
    int r0 = blockIdx.y * 64;
    int c0 = blockIdx.x * 64;
    int t = threadIdx.x;
    int ty = t >> 4, tx = t & 15;

    if (t < 64) {
        int m = c0 + t;
        const float* p;
        if (m < 1024)      p = kg1 + (size_t)(b * 1024 + m) * 256;
        else if (m < 1280) p = kg2 + (size_t)(b * 256 + m - 1024) * 256;
        else               p = kg3 + (size_t)(b * 64  + m - 1280) * 256;
        browp[t] = p;
    }
    __syncthreads();

    const float* abase = g_qg + (size_t)(b * NQ + r0) * 256;
    unsigned smem_u32 = (unsigned)__cvta_generic_to_shared(&buf[0][0]);

    auto load_stage = [&](int st, int kit) {
        int k0 = kit * 16;
        unsigned sb = smem_u32 + (unsigned)(st * SIM_STAGE_F) * 4u;
#pragma unroll
        for (int u = 0; u < 2; u++) {
            int c = t + u * 256;          // 0..511
            int reg = c >> 8;             // 0=A, 1=B
            int rc = c & 255;
            int row = rc >> 2, seg = (rc & 3) << 2;
            const float* g = (reg == 0) ? (abase + (size_t)row * 256 + k0 + seg)
                                        : (browp[row] + k0 + seg);
            unsigned dst = sb + (unsigned)((reg * 64 + row) * SLD + seg) * 4u;
            cpa16(dst, g);
        }
        cpa_commit();
    };

    float acc[4][4];
#pragma unroll
    for (int i = 0; i < 4; i++)
#pragma unroll
        for (int j = 0; j < 4; j++) acc[i][j] = 0.f;

    load_stage(0, 0);
#pragma unroll
    for (int k = 0; k < 16; k++) {
        cpa_wait0();
        __syncthreads();
        if (k + 1 < 16) load_stage((k + 1) & 1, k + 1);
        const float* As = buf[k & 1];
        const float* Bs = As + 64 * SLD;
#pragma unroll
        for (int kk = 0; kk < 16; kk++) {
            float a_[4], b_[4];
#pragma unroll
            for (int i = 0; i < 4; i++) a_[i] = As[(ty * 4 + i) * SLD + kk];
#pragma unroll
            for (int j = 0; j < 4; j++) b_[j] = Bs[(tx * 4 + j) * SLD + kk];
#pragma unroll
            for (int i = 0; i < 4; i++)
#pragma unroll
                for (int j = 0; j < 4; j++) acc[i][j] += a_[i] * b_[j];
        }
    }
#pragma unroll
    for (int i = 0; i < 4; i++)
#pragma unroll
        for (int j = 0; j < 4; j++)
            g_sim[(size_t)(b * NQ + r0 + ty * 4 + i) * NKW + c0 + tx * 4 + j] = acc[i][j];
}

// ---------------- top-32 per row: one warp per row, register-resident ----------------
__global__ void __launch_bounds__(128) topk_kernel() {
    int r = blockIdx.x * 4 + (threadIdx.x >> 5);   // 4 rows per block
    int lane = threadIdx.x & 31;
    const float* row = g_sim + (size_t)r * NKW;
    float v[42];
#pragma unroll
    for (int i = 0; i < 42; i++) v[i] = row[i * 32 + lane];
    unsigned long long used = 0ull;
    for (int it = 0; it < TOPK; it++) {
        float bv = -1e38f; int bidx = 0;
#pragma unroll
        for (int i = 0; i < 42; i++) {
            bool ok = !((used >> i) & 1ull);
            if (ok && v[i] > bv) { bv = v[i]; bidx = i; }
        }
        int gi = bidx * 32 + lane;
#pragma unroll
        for (int off = 16; off; off >>= 1) {
            float ov = __shfl_down_sync(FULLMASK, bv, off);
            int   oi = __shfl_down_sync(FULLMASK, gi, off);
            if (ov > bv || (ov == bv && oi < gi)) { bv = ov; gi = oi; }
        }
        gi = __shfl_sync(FULLMASK, gi, 0);
        if (lane == 0) g_top[r * TOPK + it] = gi;
        if ((gi & 31) == lane) used |= 1ull << (gi >> 5);
    }
}

// ---------------- greedy assignment (1 warp per batch, 32 cached candidates/row) ----------------
__global__ void greedy_kernel() {
    extern __shared__ unsigned short tops[];       // NQ * TOPK (64 KB dynamic)
    __shared__ unsigned used[42];
    int b = blockIdx.x;
    int lane = threadIdx.x;
    for (int i = lane; i < NQ * TOPK; i += 32) tops[i] = (unsigned short)g_top[b * NQ * TOPK + i];
    for (int i = lane; i < 42; i += 32) used[i] = 0u;
    __syncwarp();

    int cand = (int)tops[lane];                    // prefetch row 0 (one cand per lane)
    for (int n = 0; n < NQ; n++) {
        int ncand = (n + 1 < NQ) ? (int)tops[(n + 1) * TOPK + lane] : 0;
        bool fr = !((used[cand >> 5] >> (cand & 31)) & 1);
        unsigned bal = __ballot_sync(FULLMASK, fr);
        int chosen;
        if (bal) {
            int j = __ffs(bal) - 1;
            chosen = __shfl_sync(FULLMASK, cand, j);
        } else {
            const float* row = g_sim + ((size_t)b * NQ + n) * NKW;
            float bv = -1e38f; int bi = NKW;
            for (int m = lane; m < NKW; m += 32) {
                if (!((used[m >> 5] >> (m & 31)) & 1)) {
                    float vv = row[m];
                    if (vv > bv) { bv = vv; bi = m; }
                }
            }
#pragma unroll
            for (int off = 16; off; off >>= 1) {
                float ov = __shfl_down_sync(FULLMASK, bv, off);
                int   oi = __shfl_down_sync(FULLMASK, bi, off);
                if (ov > bv || (ov == bv && oi < bi)) { bv = ov; bi = oi; }
            }
            chosen = __shfl_sync(FULLMASK, bi, 0);
        }
        if (lane == 0) {
            used[chosen >> 5] |= 1u << (chosen & 31);
            g_idx[b * NQ + n] = chosen;
        }
        __syncwarp();
        cand = ncand;
    }
}

// ---------------- gather assigned k windows -> half (float4 per thread) ----------------
__global__ void __launch_bounds__(256) pack_k_kernel(const float* __restrict__ k1,
                                                     const float* __restrict__ k2,
                                                     const float* __restrict__ k3) {
    size_t gid = (size_t)blockIdx.x * 256 + threadIdx.x;  // each handles 4 elems
    int c = (int)(gid & 63) << 2;
    int rest = (int)(gid >> 6);
    int n = rest & 63, w = rest >> 6;
    int b = w >> 10;
    int win = g_idx[w];
    const float* src;
    if (win < 1024)      src = k1 + ((size_t)(b * 1024 + win) * 64 + n) * 256 + c;
    else if (win < 1280) src = k2 + ((size_t)(b * 256 + win - 1024) * 64 + n) * 256 + c;
    else                 src = k3 + ((size_t)(b * 64 + win - 1280) * 64 + n) * 256 + c;
    float4 v = *(const float4*)src;
    __half h[4] = {__float2half(v.x), __float2half(v.y), __float2half(v.z), __float2half(v.w)};
    *(float2*)(g_kwh + gid * 4) = *(float2*)h;
}

// ---------------- GEMM v5: 4 warps, 64x64 warp tiles, cp.async 2-stage ----------------
// MODE 0: half out = (acc+bias)*scale   MODE 1: half out = acc+bias (dual-output capable)
// MODE 2: float out = resid + acc + bias
template<int MODE>
__global__ void __launch_bounds__(128, 2) gemm5_kernel(const __half* __restrict__ A,
                                                       const __half* __restrict__ W,
                                                       const float* __restrict__ bias,
                                                       const float* __restrict__ bias2,
                                                       const float* __restrict__ resid,
                                                       void* __restrict__ out,
                                                       void* __restrict__ out2,
                                                       float scale) {
    extern __shared__ __half sm[];
    int t = threadIdx.x;
    int wid = t >> 5, lane = t & 31;
    int wm = wid >> 1, wn = wid & 1;                    // 2x2 warps, each 64x64
    int m0 = blockIdx.y * BM;
    int n0 = blockIdx.x * BN;
    unsigned smem_u32 = (unsigned)__cvta_generic_to_shared(sm);

    const __half* Ag = A + (size_t)m0 * 256;
    const __half* Wg = W + (size_t)n0 * 256;

    auto load_stage = [&](int st, int kit) {
        int k0 = kit * BK;
        unsigned sa = smem_u32 + (unsigned)(st * STAGE_HALFS) * 2u;
        unsigned sb = sa + (unsigned)(128 * LDT) * 2u;
#pragma unroll
        for (int u = 0; u < 8; u++) {
            int c = t + u * 128;                        // 0..1023
            int row = c >> 3, seg = (c & 7) << 3;       // seg in halfs
            cpa16(sa + (unsigned)(row * LDT + seg) * 2u, Ag + (size_t)row * 256 + k0 + seg);
            cpa16(sb + (unsigned)(row * LDT + seg) * 2u, Wg + (size_t)row * 256 + k0 + seg);
        }
        cpa_commit();
    };

    wmma::fragment<wmma::accumulator, 16, 16, 16, float> acc[4][4];
#pragma unroll
    for (int i = 0; i < 4; i++)
#pragma unroll
        for (int j = 0; j < 4; j++) wmma::fill_fragment(acc[i][j], 0.f);

    load_stage(0, 0);
#pragma unroll
    for (int k = 0; k < NKIT; k++) {
        cpa_wait0();
        __syncthreads();
        if (k + 1 < NKIT) load_stage((k + 1) & 1, k + 1);

        const __half* As = sm + (size_t)(k & 1) * STAGE_HALFS;
        const __half* Bs = As + 128 * LDT;
#pragma unroll
        for (int kk = 0; kk < BK; kk += 16) {
            wmma::fragment<wmma::matrix_a, 16, 16, 16, __half, wmma::row_major> a[4];
#pragma unroll
            for (int i = 0; i < 4; i++)
                wmma::load_matrix_sync(a[i], As + (wm * 64 + i * 16) * LDT + kk, LDT);
#pragma unroll
            for (int j = 0; j < 4; j++) {
                wmma::fragment<wmma::matrix_b, 16, 16, 16, __half, wmma::col_major> b;
                wmma::load_matrix_sync(b, Bs + (wn * 64 + j * 16) * LDT + kk, LDT);
#pragma unroll
                for (int i = 0; i < 4; i++)
                    wmma::mma_sync(acc[i][j], a[i], b, acc[i][j]);
            }
        }
    }
    __syncthreads();   // stages now dead -> reuse for epilogue staging

    const float* biasE = bias;
    void* outE = out;
    int nsub = 0;
    if (MODE == 1 && bias2 != nullptr && n0 >= 256) { biasE = bias2; outE = out2; nsub = 256; }

    float* wstg = (float*)sm + wid * 320;               // 16x20 floats per warp
    int r = lane >> 1, cs = (lane & 1) << 3;
#pragma unroll
    for (int i = 0; i < 4; i++)
#pragma unroll
        for (int j = 0; j < 4; j++) {
            wmma::store_matrix_sync(wstg, acc[i][j], 20, wmma::mem_row_major);
            __syncwarp();
            int m = m0 + wm * 64 + i * 16 + r;
            int n = n0 + wn * 64 + j * 16 + cs;
            int nc = n - nsub;
            size_t off = (size_t)m * 256 + nc;
            float v[8];
#pragma unroll
            for (int c = 0; c < 8; c++) v[c] = wstg[r * 20 + cs + c] + biasE[nc + c];
            if (MODE == 2) {
                float4 r0 = *(const float4*)(resid + off);
                float4 r1 = *(const float4*)(resid + off + 4);
                float4 w0 = {r0.x + v[0], r0.y + v[1], r0.z + v[2], r0.w + v[3]};
                float4 w1 = {r1.x + v[4], r1.y + v[5], r1.z + v[6], r1.w + v[7]};
                float* op = (float*)outE + off;
                *(float4*)op = w0; *(float4*)(op + 4) = w1;
            } else {
                __half h[8];
#pragma unroll
                for (int c = 0; c < 8; c++)
                    h[c] = __float2half(MODE == 0 ? v[c] * scale : v[c]);
                *(float4*)((__half*)outE + off) = *(float4*)h;
            }
            __syncwarp();
        }
}

// ---------------- attention per (window, head), smem-staged ----------------
__global__ void __launch_bounds__(256) attn_kernel(const float* __restrict__ qin) {
    __shared__ __half qs[64 * 40], ks[64 * 40], vs[64 * 40];
    __shared__ float  Ssm[64 * 68];
    __shared__ __half Psm[64 * 72];

    int w = blockIdx.x >> 3;
    int head = blockIdx.x & 7;
    int t = threadIdx.x;
    int wid = t >> 5;

    const __half* qb = g_qh + (size_t)w * 64 * 256 + head * 32;
    const __half* kb = g_kh + (size_t)w * 64 * 256 + head * 32;
    const __half* vb = g_vh + (size_t)w * 64 * 256 + head * 32;

    {
        int row = t >> 2, seg = (t & 3) << 3;
        *(float4*)(qs + row * 40 + seg) = *(const float4*)(qb + (size_t)row * 256 + seg);
        *(float4*)(ks + row * 40 + seg) = *(const float4*)(kb + (size_t)row * 256 + seg);
        *(float4*)(vs + row * 40 + seg) = *(const float4*)(vb + (size_t)row * 256 + seg);
    }
    __syncthreads();

#pragma unroll
    for (int tt = 0; tt < 2; tt++) {
        int tile = wid + tt * 8;
        int tr = tile >> 2, tc = tile & 3;
        wmma::fragment<wmma::accumulator, 16, 16, 16, float> acc;
        wmma::fill_fragment(acc, 0.f);
#pragma unroll
        for (int kk = 0; kk < 32; kk += 16) {
            wmma::fragment<wmma::matrix_a, 16, 16, 16, __half, wmma::row_major> a;
            wmma::fragment<wmma::matrix_b, 16, 16, 16, __half, wmma::col_major> b;
            wmma::load_matrix_sync(a, qs + (tr * 16) * 40 + kk, 40);
            wmma::load_matrix_sync(b, ks + (tc * 16) * 40 + kk, 40);
            wmma::mma_sync(acc, a, b, acc);
        }
        wmma::store_matrix_sync(Ssm + tr * 16 * 68 + tc * 16, acc, 68, wmma::mem_row_major);
    }
    __syncthreads();

    {
        int r = t >> 2, sub = t & 3;
        const float* brow = g_bias + head * 4096 + r * 64 + sub * 16;
        float vals[16];
        float mx = -1e38f;
#pragma unroll
        for (int i = 0; i < 16; i++) {
            vals[i] = Ssm[r * 68 + sub * 16 + i] + brow[i];
            mx = fmaxf(mx, vals[i]);
        }
        mx = fmaxf(mx, __shfl_xor_sync(FULLMASK, mx, 1));
        mx = fmaxf(mx, __shfl_xor_sync(FULLMASK, mx, 2));
        float sum = 0.f;
#pragma unroll
        for (int i = 0; i < 16; i++) {
            vals[i] = __expf(vals[i] - mx);
            sum += vals[i];
        }
        sum += __shfl_xor_sync(FULLMASK, sum, 1);
        sum += __shfl_xor_sync(FULLMASK, sum, 2);
        float inv = 1.0f / sum;
#pragma unroll
        for (int i = 0; i < 16; i++)
            Psm[r * 72 + sub * 16 + i] = __float2half(vals[i] * inv);
    }
    __syncthreads();

    {
        int tr = wid >> 1, tc = wid & 1;
        wmma::fragment<wmma::accumulator, 16, 16, 16, float> acc;
        wmma::fill_fragment(acc, 0.f);
#pragma unroll
        for (int mm = 0; mm < 64; mm += 16) {
            wmma::fragment<wmma::matrix_a, 16, 16, 16, __half, wmma::row_major> a;
            wmma::fragment<wmma::matrix_b, 16, 16, 16, __half, wmma::row_major> b;
            wmma::load_matrix_sync(a, Psm + tr * 16 * 72 + mm, 72);
            wmma::load_matrix_sync(b, vs + mm * 40 + tc * 16, 40);
            wmma::mma_sync(acc, a, b, acc);
        }
        wmma::store_matrix_sync(Ssm + tr * 16 * 36 + tc * 16, acc, 36, wmma::mem_row_major);
    }
    __syncthreads();

    {
        int b = w >> 10, hg = (w >> 5) & 31, wg = w & 31;
#pragma unroll
        for (int e0 = 0; e0 < 8; e0++) {
            int e = t * 8 + e0;
            int n = e >> 5, d = e & 31;
            int i = n >> 3, j = n & 7;
            size_t pix = (size_t)(b * 256 + hg * 8 + i) * 256 + wg * 8 + j;
            size_t off = pix * 256 + head * 32 + d;
            g_x[off] = qin[off] + Ssm[n * 36 + d];
        }
    }
}

// ---------------- LayerNorm -> half ----------------
__global__ void __launch_bounds__(256) ln_kernel(const float* __restrict__ lg,
                                                 const float* __restrict__ lb) {
    int row = blockIdx.x * 8 + (threadIdx.x >> 5);
    int lane = threadIdx.x & 31;
    const float* xr = g_x + (size_t)row * 256;
    float4 v0 = *(const float4*)(xr + lane * 8);
    float4 v1 = *(const float4*)(xr + lane * 8 + 4);
    float s = v0.x + v0.y + v0.z + v0.w + v1.x + v1.y + v1.z + v1.w;
#pragma unroll
    for (int off = 16; off; off >>= 1) s += __shfl_xor_sync(FULLMASK, s, off);
    float mu = s * (1.0f / 256.0f);
    float vs = 0.f;
    float d0[8] = {v0.x - mu, v0.y - mu, v0.z - mu, v0.w - mu,
                   v1.x - mu, v1.y - mu, v1.z - mu, v1.w - mu};
#pragma unroll
    for (int i = 0; i < 8; i++) vs += d0[i] * d0[i];
#pragma unroll
    for (int off = 16; off; off >>= 1) vs += __shfl_xor_sync(FULLMASK, vs, off);
    float rstd = rsqrtf(vs * (1.0f / 256.0f) + 1e-5f);
    __half* o = g_ln + (size_t)row * 256 + lane * 8;
#pragma unroll
    for (int i = 0; i < 8; i++) {
        int c = lane * 8 + i;
        o[i] = __float2half(d0[i] * rstd * lg[c] + lb[c]);
    }
}

// ---------------- launch ----------------
extern "C" void kernel_launch(void* const* d_in, const int* in_sizes, int n_in,
                              void* d_out, int out_size) {
    const float* q   = (const float*)d_in[0];
    const float* k1  = (const float*)d_in[1];
    const float* k2  = (const float*)d_in[2];
    const float* k3  = (const float*)d_in[3];
    const float* kg1 = (const float*)d_in[4];
    const float* kg2 = (const float*)d_in[5];
    const float* kg3 = (const float*)d_in[6];
    const float* rbt = (const float*)d_in[7];
    const float* Wq  = (const float*)d_in[8];
    const float* bq  = (const float*)d_in[9];
    const float* Wk  = (const float*)d_in[10];
    const float* bk  = (const float*)d_in[11];
    const float* Wv  = (const float*)d_in[12];
    const float* bv  = (const float*)d_in[13];
    const float* lng = (const float*)d_in[14];
    const float* lnb = (const float*)d_in[15];
    const float* Wp  = (const float*)d_in[16];
    const float* bp  = (const float*)d_in[17];
    float* out = (float*)d_out;

    __half *dWq, *dWkv, *dWp, *dqwh, *dkwh, *dqh, *dkh, *dvh, *dln;
    float *dx;
    cudaGetSymbolAddress((void**)&dWq,  g_Wq);
    cudaGetSymbolAddress((void**)&dWkv, g_Wkv);
    cudaGetSymbolAddress((void**)&dWp,  g_Wp);
    cudaGetSymbolAddress((void**)&dqwh, g_qwh);
    cudaGetSymbolAddress((void**)&dkwh, g_kwh);
    cudaGetSymbolAddress((void**)&dqh,  g_qh);
    cudaGetSymbolAddress((void**)&dkh,  g_kh);
    cudaGetSymbolAddress((void**)&dvh,  g_vh);
    cudaGetSymbolAddress((void**)&dln,  g_ln);
    cudaGetSymbolAddress((void**)&dx,   g_x);

    cudaFuncSetAttribute(gemm5_kernel<0>, cudaFuncAttributeMaxDynamicSharedMemorySize, SMEM_GEMM);
    cudaFuncSetAttribute(gemm5_kernel<1>, cudaFuncAttributeMaxDynamicSharedMemorySize, SMEM_GEMM);
    cudaFuncSetAttribute(gemm5_kernel<2>, cudaFuncAttributeMaxDynamicSharedMemorySize, SMEM_GEMM);
    cudaFuncSetAttribute(greedy_kernel, cudaFuncAttributeMaxDynamicSharedMemorySize, SMEM_GREEDY);

    const float scale = 0.17677669529663687f;   // 32^-0.5

    // fork-join (proven-clean single extra stream + 2 events): latency-bound
    // greedy chain overlaps the throughput-bound weight-conv + q-projection.
    cudaStream_t s2;
    cudaEvent_t e1, e2;
    cudaStreamCreateWithFlags(&s2, cudaStreamNonBlocking);
    cudaEventCreateWithFlags(&e1, cudaEventDisableTiming);
    cudaEventCreateWithFlags(&e2, cudaEventDisableTiming);

    pack_qg_kernel<<<NWIN, 256>>>(q);                              // 1
    sim_kernel<<<dim3(21, 16, 2), 256>>>(kg1, kg2, kg3);           // 2
    topk_kernel<<<NWIN / 4, 128>>>();                              // 3
    cudaEventRecord(e1, 0);

    cudaStreamWaitEvent(s2, e1, 0);
    greedy_kernel<<<2, 32, SMEM_GREEDY, s2>>>();                   // 4 <- ncu capture slot
    pack_k_kernel<<<MROWS * 64 / 256, 256, 0, s2>>>(k1, k2, k3);   // 5
    cudaEventRecord(e2, s2);

    conv_w_kernel<<<1024, 256>>>(Wq, Wk, Wv, Wp);                  // 6
    bias_kernel<<<128, 256>>>(rbt);                                // 7
    gemm5_kernel<0><<<dim3(2, 1024), 128, SMEM_GEMM>>>(dqwh, dWq, bq, nullptr, nullptr,
                                                       dqh, nullptr, scale);   // 8

    cudaStreamWaitEvent(0, e2, 0);
    gemm5_kernel<1><<<dim3(4, 1024), 128, SMEM_GEMM>>>(dkwh, dWkv, bk, bv, nullptr,
                                                       dkh, dvh, 0.f);

    attn_kernel<<<NWIN * 8, 256>>>(q);
    ln_kernel<<<MROWS / 8, 256>>>(lng, lnb);
    gemm5_kernel<2><<<dim3(2, 1024), 128, SMEM_GEMM>>>(dln, dWp, bp, nullptr, dx,
                                                       out, nullptr, 0.f);
}

// round 16
// speedup vs baseline: 1.0831x; 1.0532x over previous
#include <cuda_runtime.h>
#include <cuda_fp16.h>
#include <mma.h>
#include <cstdint>

using namespace nvcuda;

#define FULLMASK 0xffffffffu
#define B2   2
#define CDIM 256
#define NQ   1024
#define NKW  1344
#define TOPK 32
#define NWIN 2048          // B2*NQ
#define MROWS (NWIN*64)    // 131072

// pipelined GEMM geometry (v5: 4 warps, 64x64 warp tiles, BK=64, 2 stages)
#define BM 128
#define BN 128
#define BK 64
#define NKIT (CDIM / BK)   // 4
#define LDT 72             // padded half stride per stage row
#define STAGE_HALFS (256 * LDT)             // A(128 rows)+B(128 rows)
#define SMEM_GEMM (2 * STAGE_HALFS * 2)     // 73728 bytes
#define SMEM_GREEDY (NQ * TOPK * 2)         // 65536 bytes (dynamic)

// sim pipeline geometry
#define SLD 20             // padded float stride (16 data + 4 pad)
#define SIM_STAGE_F (2 * 64 * SLD)          // A+B rows per stage (floats)

// ---------------- device scratch ----------------
__device__ float  g_qg [B2*NQ*CDIM];
__device__ float  g_sim[B2*NQ*NKW];
__device__ int    g_top[B2*NQ*TOPK];
__device__ int    g_idx[B2*NQ];
__device__ __half g_Wq[CDIM*CDIM], g_Wkv[2*CDIM*CDIM], g_Wp[CDIM*CDIM];
__device__ __half g_qwh[(size_t)MROWS*CDIM];
__device__ __half g_kwh[(size_t)MROWS*CDIM];
__device__ __half g_qh [(size_t)MROWS*CDIM];
__device__ __half g_kh [(size_t)MROWS*CDIM];
__device__ __half g_vh [(size_t)MROWS*CDIM];
__device__ float  g_x  [(size_t)MROWS*CDIM];
__device__ __half g_ln [(size_t)MROWS*CDIM];
__device__ float  g_bias[8*64*64];

// ---------------- cp.async helpers ----------------
__device__ __forceinline__ void cpa16(unsigned saddr, const void* gaddr) {
    asm volatile("cp.async.cg.shared.global [%0], [%1], 16;" :: "r"(saddr), "l"(gaddr));
}
__device__ __forceinline__ void cpa_commit() {
    asm volatile("cp.async.commit_group;");
}
__device__ __forceinline__ void cpa_wait0() {
    asm volatile("cp.async.wait_group 0;" ::: "memory");
}

// ---------------- prep kernels ----------------
__global__ void conv_w_kernel(const float* __restrict__ Wq, const float* __restrict__ Wk,
                              const float* __restrict__ Wv, const float* __restrict__ Wp) {
    int i = blockIdx.x * 256 + threadIdx.x;   // 4*65536
    int j = i & 65535;
    switch (i >> 16) {
        case 0: g_Wq[j] = __float2half(Wq[j]); break;
        case 1: g_Wkv[j] = __float2half(Wk[j]); break;              // rows 0..255
        case 2: g_Wkv[65536 + j] = __float2half(Wv[j]); break;      // rows 256..511
        default: g_Wp[j] = __float2half(Wp[j]); break;
    }
}

__global__ void bias_kernel(const float* __restrict__ table) {
    int e = blockIdx.x * 256 + threadIdx.x;   // 32768
    int h = e >> 12, n = (e >> 6) & 63, m = e & 63;
    int rp = ((n >> 3) - (m >> 3) + 7) * 15 + ((n & 7) - (m & 7) + 7);
    g_bias[e] = table[rp * 8 + h];
}

// fused: window-partition q -> half, and window-mean -> g_qg (single q read)
__global__ void __launch_bounds__(256) pack_qg_kernel(const float* __restrict__ q) {
    int w = blockIdx.x;                        // 0..2047
    int c = threadIdx.x;
    int b = w >> 10, hg = (w >> 5) & 31, wg = w & 31;
    const float* base = q + (((size_t)(b * 256 + hg * 8)) * 256 + wg * 8) * 256 + c;
    __half* dst = g_qwh + (size_t)w * 64 * 256 + c;
    float s = 0.f;
#pragma unroll
    for (int i = 0; i < 8; i++)
#pragma unroll
        for (int j = 0; j < 8; j++) {
            float v = base[(size_t)(i * 256 + j) * 256];
            s += v;
            dst[(size_t)(i * 8 + j) * 256] = __float2half(v);
        }
    g_qg[(size_t)w * 256 + c] = s * (1.0f / 64.0f);
}

// ---------------- sim = qg @ kg^T (fp32, cp.async 2-stage) ----------------
__global__ void __launch_bounds__(256) sim_kernel(const float* __restrict__ kg1,
                                                  const float* __restrict__ kg2,
                                                  const float* __restrict__ kg3) {
    __shared__ float buf[2][SIM_STAGE_F];
    __shared__ const float* browp[64];
    int b = blockIdx.z;
    int r0 = blockIdx.y * 64;
    int c0 = blockIdx.x * 64;
    int t = threadIdx.x;
    int ty = t >> 4, tx = t & 15;

    if (t < 64) {
        int m = c0 + t;
        const float* p;
        if (m < 1024)      p = kg1 + (size_t)(b * 1024 + m) * 256;
        else if (m < 1280) p = kg2 + (size_t)(b * 256 + m - 1024) * 256;
        else               p = kg3 + (size_t)(b * 64  + m - 1280) * 256;
        browp[t] = p;
    }
    __syncthreads();

    const float* abase = g_qg + (size_t)(b * NQ + r0) * 256;
    unsigned smem_u32 = (unsigned)__cvta_generic_to_shared(&buf[0][0]);

    auto load_stage = [&](int st, int kit) {
        int k0 = kit * 16;
        unsigned sb = smem_u32 + (unsigned)(st * SIM_STAGE_F) * 4u;
#pragma unroll
        for (int u = 0; u < 2; u++) {
            int c = t + u * 256;          // 0..511
            int reg = c >> 8;             // 0=A, 1=B
            int rc = c & 255;
            int row = rc >> 2, seg = (rc & 3) << 2;
            const float* g = (reg == 0) ? (abase + (size_t)row * 256 + k0 + seg)
                                        : (browp[row] + k0 + seg);
            unsigned dst = sb + (unsigned)((reg * 64 + row) * SLD + seg) * 4u;
            cpa16(dst, g);
        }
        cpa_commit();
    };

    float acc[4][4];
#pragma unroll
    for (int i = 0; i < 4; i++)
#pragma unroll
        for (int j = 0; j < 4; j++) acc[i][j] = 0.f;

    load_stage(0, 0);
#pragma unroll
    for (int k = 0; k < 16; k++) {
        cpa_wait0();
        __syncthreads();
        if (k + 1 < 16) load_stage((k + 1) & 1, k + 1);
        const float* As = buf[k & 1];
        const float* Bs = As + 64 * SLD;
#pragma unroll
        for (int kk = 0; kk < 16; kk++) {
            float a_[4], b_[4];
#pragma unroll
            for (int i = 0; i < 4; i++) a_[i] = As[(ty * 4 + i) * SLD + kk];
#pragma unroll
            for (int j = 0; j < 4; j++) b_[j] = Bs[(tx * 4 + j) * SLD + kk];
#pragma unroll
            for (int i = 0; i < 4; i++)
#pragma unroll
                for (int j = 0; j < 4; j++) acc[i][j] += a_[i] * b_[j];
        }
    }
#pragma unroll
    for (int i = 0; i < 4; i++)
#pragma unroll
        for (int j = 0; j < 4; j++)
            g_sim[(size_t)(b * NQ + r0 + ty * 4 + i) * NKW + c0 + tx * 4 + j] = acc[i][j];
}

// ---------------- top-32 per row: one warp per row, register-resident ----------------
__global__ void __launch_bounds__(128) topk_kernel() {
    int r = blockIdx.x * 4 + (threadIdx.x >> 5);   // 4 rows per block
    int lane = threadIdx.x & 31;
    const float* row = g_sim + (size_t)r * NKW;
    float v[42];
#pragma unroll
    for (int i = 0; i < 42; i++) v[i] = row[i * 32 + lane];
    unsigned long long used = 0ull;
    for (int it = 0; it < TOPK; it++) {
        float bv = -1e38f; int bidx = 0;
#pragma unroll
        for (int i = 0; i < 42; i++) {
            bool ok = !((used >> i) & 1ull);
            if (ok && v[i] > bv) { bv = v[i]; bidx = i; }
        }
        int gi = bidx * 32 + lane;
#pragma unroll
        for (int off = 16; off; off >>= 1) {
            float ov = __shfl_down_sync(FULLMASK, bv, off);
            int   oi = __shfl_down_sync(FULLMASK, gi, off);
            if (ov > bv || (ov == bv && oi < gi)) { bv = ov; gi = oi; }
        }
        gi = __shfl_sync(FULLMASK, gi, 0);
        if (lane == 0) g_top[r * TOPK + it] = gi;
        if ((gi & 31) == lane) used |= 1ull << (gi >> 5);
    }
}

// ---------------- greedy assignment: register-distributed used bitmap ----------------
// lane l owns all columns c with (c & 31) == l; ownership bit = c >> 5 (0..41).
// Candidate check = shfl.idx of owner's 64-bit word; fallback scan checks own word only.
__global__ void greedy_kernel() {
    extern __shared__ unsigned short tops[];       // NQ * TOPK (64 KB dynamic)
    int b = blockIdx.x;
    int lane = threadIdx.x;
    for (int i = lane; i < NQ * TOPK; i += 32) tops[i] = (unsigned short)g_top[b * NQ * TOPK + i];
    __syncwarp();

    unsigned long long used64 = 0ull;
    int cand = (int)tops[lane];                    // prefetch row 0 (one cand per lane)
    for (int n = 0; n < NQ; n++) {
        int ncand = (n + 1 < NQ) ? (int)tops[(n + 1) * TOPK + lane] : 0;
        unsigned long long w = __shfl_sync(FULLMASK, used64, cand & 31);
        bool fr = !((w >> (cand >> 5)) & 1ull);
        unsigned bal = __ballot_sync(FULLMASK, fr);
        int chosen;
        if (bal) {
            chosen = __shfl_sync(FULLMASK, cand, __ffs(bal) - 1);
        } else {
            const float* row = g_sim + ((size_t)b * NQ + n) * NKW;
            float bv = -1e38f; int bi = NKW;
#pragma unroll
            for (int i = 0; i < 42; i++) {
                if (!((used64 >> i) & 1ull)) {
                    float vv = row[i * 32 + lane];
                    if (vv > bv) { bv = vv; bi = i * 32 + lane; }
                }
            }
#pragma unroll
            for (int off = 16; off; off >>= 1) {
                float ov = __shfl_down_sync(FULLMASK, bv, off);
                int   oi = __shfl_down_sync(FULLMASK, bi, off);
                if (ov > bv || (ov == bv && oi < bi)) { bv = ov; bi = oi; }
            }
            chosen = __shfl_sync(FULLMASK, bi, 0);
        }
        if ((chosen & 31) == lane) used64 |= 1ull << (chosen >> 5);
        if (lane == 0) g_idx[b * NQ + n] = chosen;
        cand = ncand;
    }
}

// ---------------- gather assigned k windows -> half (float4 per thread) ----------------
__global__ void __launch_bounds__(256) pack_k_kernel(const float* __restrict__ k1,
                                                     const float* __restrict__ k2,
                                                     const float* __restrict__ k3) {
    size_t gid = (size_t)blockIdx.x * 256 + threadIdx.x;  // each handles 4 elems
    int c = (int)(gid & 63) << 2;
    int rest = (int)(gid >> 6);
    int n = rest & 63, w = rest >> 6;
    int b = w >> 10;
    int win = g_idx[w];
    const float* src;
    if (win < 1024)      src = k1 + ((size_t)(b * 1024 + win) * 64 + n) * 256 + c;
    else if (win < 1280) src = k2 + ((size_t)(b * 256 + win - 1024) * 64 + n) * 256 + c;
    else                 src = k3 + ((size_t)(b * 64 + win - 1280) * 64 + n) * 256 + c;
    float4 v = *(const float4*)src;
    __half h[4] = {__float2half(v.x), __float2half(v.y), __float2half(v.z), __float2half(v.w)};
    *(float2*)(g_kwh + gid * 4) = *(float2*)h;
}

// ---------------- GEMM v5: 4 warps, 64x64 warp tiles, cp.async 2-stage ----------------
// MODE 0: half out = (acc+bias)*scale   MODE 1: half out = acc+bias (dual-output capable)
// MODE 2: float out = resid + acc + bias
template<int MODE>
__global__ void __launch_bounds__(128, 2) gemm5_kernel(const __half* __restrict__ A,
                                                       const __half* __restrict__ W,
                                                       const float* __restrict__ bias,
                                                       const float* __restrict__ bias2,
                                                       const float* __restrict__ resid,
                                                       void* __restrict__ out,
                                                       void* __restrict__ out2,
                                                       float scale) {
    extern __shared__ __half sm[];
    int t = threadIdx.x;
    int wid = t >> 5, lane = t & 31;
    int wm = wid >> 1, wn = wid & 1;                    // 2x2 warps, each 64x64
    int m0 = blockIdx.y * BM;
    int n0 = blockIdx.x * BN;
    unsigned smem_u32 = (unsigned)__cvta_generic_to_shared(sm);

    const __half* Ag = A + (size_t)m0 * 256;
    const __half* Wg = W + (size_t)n0 * 256;

    auto load_stage = [&](int st, int kit) {
        int k0 = kit * BK;
        unsigned sa = smem_u32 + (unsigned)(st * STAGE_HALFS) * 2u;
        unsigned sb = sa + (unsigned)(128 * LDT) * 2u;
#pragma unroll
        for (int u = 0; u < 8; u++) {
            int c = t + u * 128;                        // 0..1023
            int row = c >> 3, seg = (c & 7) << 3;       // seg in halfs
            cpa16(sa + (unsigned)(row * LDT + seg) * 2u, Ag + (size_t)row * 256 + k0 + seg);
            cpa16(sb + (unsigned)(row * LDT + seg) * 2u, Wg + (size_t)row * 256 + k0 + seg);
        }
        cpa_commit();
    };

    wmma::fragment<wmma::accumulator, 16, 16, 16, float> acc[4][4];
#pragma unroll
    for (int i = 0; i < 4; i++)
#pragma unroll
        for (int j = 0; j < 4; j++) wmma::fill_fragment(acc[i][j], 0.f);

    load_stage(0, 0);
#pragma unroll
    for (int k = 0; k < NKIT; k++) {
        cpa_wait0();
        __syncthreads();
        if (k + 1 < NKIT) load_stage((k + 1) & 1, k + 1);

        const __half* As = sm + (size_t)(k & 1) * STAGE_HALFS;
        const __half* Bs = As + 128 * LDT;
#pragma unroll
        for (int kk = 0; kk < BK; kk += 16) {
            wmma::fragment<wmma::matrix_a, 16, 16, 16, __half, wmma::row_major> a[4];
#pragma unroll
            for (int i = 0; i < 4; i++)
                wmma::load_matrix_sync(a[i], As + (wm * 64 + i * 16) * LDT + kk, LDT);
#pragma unroll
            for (int j = 0; j < 4; j++) {
                wmma::fragment<wmma::matrix_b, 16, 16, 16, __half, wmma::col_major> b;
                wmma::load_matrix_sync(b, Bs + (wn * 64 + j * 16) * LDT + kk, LDT);
#pragma unroll
                for (int i = 0; i < 4; i++)
                    wmma::mma_sync(acc[i][j], a[i], b, acc[i][j]);
            }
        }
    }
    __syncthreads();   // stages now dead -> reuse for epilogue staging

    const float* biasE = bias;
    void* outE = out;
    int nsub = 0;
    if (MODE == 1 && bias2 != nullptr && n0 >= 256) { biasE = bias2; outE = out2; nsub = 256; }

    float* wstg = (float*)sm + wid * 320;               // 16x20 floats per warp
    int r = lane >> 1, cs = (lane & 1) << 3;
#pragma unroll
    for (int i = 0; i < 4; i++)
#pragma unroll
        for (int j = 0; j < 4; j++) {
            wmma::store_matrix_sync(wstg, acc[i][j], 20, wmma::mem_row_major);
            __syncwarp();
            int m = m0 + wm * 64 + i * 16 + r;
            int n = n0 + wn * 64 + j * 16 + cs;
            int nc = n - nsub;
            size_t off = (size_t)m * 256 + nc;
            float v[8];
#pragma unroll
            for (int c = 0; c < 8; c++) v[c] = wstg[r * 20 + cs + c] + biasE[nc + c];
            if (MODE == 2) {
                float4 r0 = *(const float4*)(resid + off);
                float4 r1 = *(const float4*)(resid + off + 4);
                float4 w0 = {r0.x + v[0], r0.y + v[1], r0.z + v[2], r0.w + v[3]};
                float4 w1 = {r1.x + v[4], r1.y + v[5], r1.z + v[6], r1.w + v[7]};
                float* op = (float*)outE + off;
                *(float4*)op = w0; *(float4*)(op + 4) = w1;
            } else {
                __half h[8];
#pragma unroll
                for (int c = 0; c < 8; c++)
                    h[c] = __float2half(MODE == 0 ? v[c] * scale : v[c]);
                *(float4*)((__half*)outE + off) = *(float4*)h;
            }
            __syncwarp();
        }
}

// ---------------- attention per (window, head), smem-staged ----------------
__global__ void __launch_bounds__(256) attn_kernel(const float* __restrict__ qin) {
    __shared__ __half qs[64 * 40], ks[64 * 40], vs[64 * 40];
    __shared__ float  Ssm[64 * 68];
    __shared__ __half Psm[64 * 72];

    int w = blockIdx.x >> 3;
    int head = blockIdx.x & 7;
    int t = threadIdx.x;
    int wid = t >> 5;

    const __half* qb = g_qh + (size_t)w * 64 * 256 + head * 32;
    const __half* kb = g_kh + (size_t)w * 64 * 256 + head * 32;
    const __half* vb = g_vh + (size_t)w * 64 * 256 + head * 32;

    {
        int row = t >> 2, seg = (t & 3) << 3;
        *(float4*)(qs + row * 40 + seg) = *(const float4*)(qb + (size_t)row * 256 + seg);
        *(float4*)(ks + row * 40 + seg) = *(const float4*)(kb + (size_t)row * 256 + seg);
        *(float4*)(vs + row * 40 + seg) = *(const float4*)(vb + (size_t)row * 256 + seg);
    }
    __syncthreads();

#pragma unroll
    for (int tt = 0; tt < 2; tt++) {
        int tile = wid + tt * 8;
        int tr = tile >> 2, tc = tile & 3;
        wmma::fragment<wmma::accumulator, 16, 16, 16, float> acc;
        wmma::fill_fragment(acc, 0.f);
#pragma unroll
        for (int kk = 0; kk < 32; kk += 16) {
            wmma::fragment<wmma::matrix_a, 16, 16, 16, __half, wmma::row_major> a;
            wmma::fragment<wmma::matrix_b, 16, 16, 16, __half, wmma::col_major> b;
            wmma::load_matrix_sync(a, qs + (tr * 16) * 40 + kk, 40);
            wmma::load_matrix_sync(b, ks + (tc * 16) * 40 + kk, 40);
            wmma::mma_sync(acc, a, b, acc);
        }
        wmma::store_matrix_sync(Ssm + tr * 16 * 68 + tc * 16, acc, 68, wmma::mem_row_major);
    }
    __syncthreads();

    {
        int r = t >> 2, sub = t & 3;
        const float* brow = g_bias + head * 4096 + r * 64 + sub * 16;
        float vals[16];
        float mx = -1e38f;
#pragma unroll
        for (int i = 0; i < 16; i++) {
            vals[i] = Ssm[r * 68 + sub * 16 + i] + brow[i];
            mx = fmaxf(mx, vals[i]);
        }
        mx = fmaxf(mx, __shfl_xor_sync(FULLMASK, mx, 1));
        mx = fmaxf(mx, __shfl_xor_sync(FULLMASK, mx, 2));
        float sum = 0.f;
#pragma unroll
        for (int i = 0; i < 16; i++) {
            vals[i] = __expf(vals[i] - mx);
            sum += vals[i];
        }
        sum += __shfl_xor_sync(FULLMASK, sum, 1);
        sum += __shfl_xor_sync(FULLMASK, sum, 2);
        float inv = 1.0f / sum;
#pragma unroll
        for (int i = 0; i < 16; i++)
            Psm[r * 72 + sub * 16 + i] = __float2half(vals[i] * inv);
    }
    __syncthreads();

    {
        int tr = wid >> 1, tc = wid & 1;
        wmma::fragment<wmma::accumulator, 16, 16, 16, float> acc;
        wmma::fill_fragment(acc, 0.f);
#pragma unroll
        for (int mm = 0; mm < 64; mm += 16) {
            wmma::fragment<wmma::matrix_a, 16, 16, 16, __half, wmma::row_major> a;
            wmma::fragment<wmma::matrix_b, 16, 16, 16, __half, wmma::row_major> b;
            wmma::load_matrix_sync(a, Psm + tr * 16 * 72 + mm, 72);
            wmma::load_matrix_sync(b, vs + mm * 40 + tc * 16, 40);
            wmma::mma_sync(acc, a, b, acc);
        }
        wmma::store_matrix_sync(Ssm + tr * 16 * 36 + tc * 16, acc, 36, wmma::mem_row_major);
    }
    __syncthreads();

    {
        int b = w >> 10, hg = (w >> 5) & 31, wg = w & 31;
#pragma unroll
        for (int e0 = 0; e0 < 8; e0++) {
            int e = t * 8 + e0;
            int n = e >> 5, d = e & 31;
            int i = n >> 3, j = n & 7;
            size_t pix = (size_t)(b * 256 + hg * 8 + i) * 256 + wg * 8 + j;
            size_t off = pix * 256 + head * 32 + d;
            g_x[off] = qin[off] + Ssm[n * 36 + d];
        }
    }
}

// ---------------- LayerNorm -> half ----------------
__global__ void __launch_bounds__(256) ln_kernel(const float* __restrict__ lg,
                                                 const float* __restrict__ lb) {
    int row = blockIdx.x * 8 + (threadIdx.x >> 5);
    int lane = threadIdx.x & 31;
    const float* xr = g_x + (size_t)row * 256;
    float4 v0 = *(const float4*)(xr + lane * 8);
    float4 v1 = *(const float4*)(xr + lane * 8 + 4);
    float s = v0.x + v0.y + v0.z + v0.w + v1.x + v1.y + v1.z + v1.w;
#pragma unroll
    for (int off = 16; off; off >>= 1) s += __shfl_xor_sync(FULLMASK, s, off);
    float mu = s * (1.0f / 256.0f);
    float vs = 0.f;
    float d0[8] = {v0.x - mu, v0.y - mu, v0.z - mu, v0.w - mu,
                   v1.x - mu, v1.y - mu, v1.z - mu, v1.w - mu};
#pragma unroll
    for (int i = 0; i < 8; i++) vs += d0[i] * d0[i];
#pragma unroll
    for (int off = 16; off; off >>= 1) vs += __shfl_xor_sync(FULLMASK, vs, off);
    float rstd = rsqrtf(vs * (1.0f / 256.0f) + 1e-5f);
    __half* o = g_ln + (size_t)row * 256 + lane * 8;
#pragma unroll
    for (int i = 0; i < 8; i++) {
        int c = lane * 8 + i;
        o[i] = __float2half(d0[i] * rstd * lg[c] + lb[c]);
    }
}

// ---------------- launch ----------------
extern "C" void kernel_launch(void* const* d_in, const int* in_sizes, int n_in,
                              void* d_out, int out_size) {
    const float* q   = (const float*)d_in[0];
    const float* k1  = (const float*)d_in[1];
    const float* k2  = (const float*)d_in[2];
    const float* k3  = (const float*)d_in[3];
    const float* kg1 = (const float*)d_in[4];
    const float* kg2 = (const float*)d_in[5];
    const float* kg3 = (const float*)d_in[6];
    const float* rbt = (const float*)d_in[7];
    const float* Wq  = (const float*)d_in[8];
    const float* bq  = (const float*)d_in[9];
    const float* Wk  = (const float*)d_in[10];
    const float* bk  = (const float*)d_in[11];
    const float* Wv  = (const float*)d_in[12];
    const float* bv  = (const float*)d_in[13];
    const float* lng = (const float*)d_in[14];
    const float* lnb = (const float*)d_in[15];
    const float* Wp  = (const float*)d_in[16];
    const float* bp  = (const float*)d_in[17];
    float* out = (float*)d_out;

    __half *dWq, *dWkv, *dWp, *dqwh, *dkwh, *dqh, *dkh, *dvh, *dln;
    float *dx;
    cudaGetSymbolAddress((void**)&dWq,  g_Wq);
    cudaGetSymbolAddress((void**)&dWkv, g_Wkv);
    cudaGetSymbolAddress((void**)&dWp,  g_Wp);
    cudaGetSymbolAddress((void**)&dqwh, g_qwh);
    cudaGetSymbolAddress((void**)&dkwh, g_kwh);
    cudaGetSymbolAddress((void**)&dqh,  g_qh);
    cudaGetSymbolAddress((void**)&dkh,  g_kh);
    cudaGetSymbolAddress((void**)&dvh,  g_vh);
    cudaGetSymbolAddress((void**)&dln,  g_ln);
    cudaGetSymbolAddress((void**)&dx,   g_x);

    cudaFuncSetAttribute(gemm5_kernel<0>, cudaFuncAttributeMaxDynamicSharedMemorySize, SMEM_GEMM);
    cudaFuncSetAttribute(gemm5_kernel<1>, cudaFuncAttributeMaxDynamicSharedMemorySize, SMEM_GEMM);
    cudaFuncSetAttribute(gemm5_kernel<2>, cudaFuncAttributeMaxDynamicSharedMemorySize, SMEM_GEMM);
    cudaFuncSetAttribute(greedy_kernel, cudaFuncAttributeMaxDynamicSharedMemorySize, SMEM_GREEDY);

    const float scale = 0.17677669529663687f;   // 32^-0.5

    // fork-join (proven-clean single extra stream + 2 events): latency-bound
    // greedy chain overlaps the throughput-bound weight-conv + q-projection.
    cudaStream_t s2;
    cudaEvent_t e1, e2;
    cudaStreamCreateWithFlags(&s2, cudaStreamNonBlocking);
    cudaEventCreateWithFlags(&e1, cudaEventDisableTiming);
    cudaEventCreateWithFlags(&e2, cudaEventDisableTiming);

    pack_qg_kernel<<<NWIN, 256>>>(q);                              // 1
    sim_kernel<<<dim3(21, 16, 2), 256>>>(kg1, kg2, kg3);           // 2
    topk_kernel<<<NWIN / 4, 128>>>();                              // 3
    cudaEventRecord(e1, 0);

    cudaStreamWaitEvent(s2, e1, 0);
    greedy_kernel<<<2, 32, SMEM_GREEDY, s2>>>();                   // 4 <- ncu capture slot
    pack_k_kernel<<<MROWS * 64 / 256, 256, 0, s2>>>(k1, k2, k3);   // 5
    cudaEventRecord(e2, s2);

    conv_w_kernel<<<1024, 256>>>(Wq, Wk, Wv, Wp);                  // 6
    bias_kernel<<<128, 256>>>(rbt);                                // 7
    gemm5_kernel<0><<<dim3(2, 1024), 128, SMEM_GEMM>>>(dqwh, dWq, bq, nullptr, nullptr,
                                                       dqh, nullptr, scale);   // 8

    cudaStreamWaitEvent(0, e2, 0);
    gemm5_kernel<1><<<dim3(4, 1024), 128, SMEM_GEMM>>>(dkwh, dWkv, bk, bv, nullptr,
                                                       dkh, dvh, 0.f);

    attn_kernel<<<NWIN * 8, 256>>>(q);
    ln_kernel<<<MROWS / 8, 256>>>(lng, lnb);
    gemm5_kernel<2><<<dim3(2, 1024), 128, SMEM_GEMM>>>(dln, dWp, bp, nullptr, dx,
                                                       out, nullptr, 0.f);
}

// round 17
// speedup vs baseline: 1.0882x; 1.0047x over previous
#include <cuda_runtime.h>
#include <cuda_fp16.h>
#include <mma.h>
#include <cstdint>

using namespace nvcuda;

#define FULLMASK 0xffffffffu
#define B2   2
#define CDIM 256
#define NQ   1024
#define NKW  1344
#define TOPK 32
#define NWIN 2048          // B2*NQ
#define MROWS (NWIN*64)    // 131072

// pipelined GEMM geometry (v5: 4 warps, 64x64 warp tiles, BK=64, 2 stages)
#define BM 128
#define BN 128
#define BK 64
#define NKIT (CDIM / BK)   // 4
#define LDT 72             // padded half stride per stage row
#define STAGE_HALFS (256 * LDT)             // A(128 rows)+B(128 rows)
#define SMEM_GEMM (2 * STAGE_HALFS * 2)     // 73728 bytes
#define SMEM_GREEDY (NQ * TOPK * 2)         // 65536 bytes (dynamic)

// sim pipeline geometry
#define SLD 20             // padded float stride (16 data + 4 pad)
#define SIM_STAGE_F (2 * 64 * SLD)          // A+B rows per stage (floats)

// ---------------- device scratch ----------------
__device__ float  g_qg [B2*NQ*CDIM];
__device__ float  g_sim[B2*NQ*NKW];
__device__ int    g_top[B2*NQ*TOPK];
__device__ int    g_idx[B2*NQ];
__device__ __half g_Wq[CDIM*CDIM], g_Wkv[2*CDIM*CDIM], g_Wp[CDIM*CDIM];
__device__ __half g_qwh[(size_t)MROWS*CDIM];
__device__ __half g_kwh[(size_t)MROWS*CDIM];
__device__ __half g_qh [(size_t)MROWS*CDIM];
__device__ __half g_kh [(size_t)MROWS*CDIM];
__device__ __half g_vh [(size_t)MROWS*CDIM];
__device__ float  g_x  [(size_t)MROWS*CDIM];
__device__ __half g_ln [(size_t)MROWS*CDIM];
__device__ float  g_bias[8*64*64];

// ---------------- cp.async helpers ----------------
__device__ __forceinline__ void cpa16(unsigned saddr, const void* gaddr) {
    asm volatile("cp.async.cg.shared.global [%0], [%1], 16;" :: "r"(saddr), "l"(gaddr));
}
__device__ __forceinline__ void cpa_commit() {
    asm volatile("cp.async.commit_group;");
}
__device__ __forceinline__ void cpa_wait0() {
    asm volatile("cp.async.wait_group 0;" ::: "memory");
}

// ---------------- prep kernels ----------------
__global__ void conv_w_kernel(const float* __restrict__ Wq, const float* __restrict__ Wk,
                              const float* __restrict__ Wv, const float* __restrict__ Wp) {
    int i = blockIdx.x * 256 + threadIdx.x;   // 4*65536
    int j = i & 65535;
    switch (i >> 16) {
        case 0: g_Wq[j] = __float2half(Wq[j]); break;
        case 1: g_Wkv[j] = __float2half(Wk[j]); break;              // rows 0..255
        case 2: g_Wkv[65536 + j] = __float2half(Wv[j]); break;      // rows 256..511
        default: g_Wp[j] = __float2half(Wp[j]); break;
    }
}

__global__ void bias_kernel(const float* __restrict__ table) {
    int e = blockIdx.x * 256 + threadIdx.x;   // 32768
    int h = e >> 12, n = (e >> 6) & 63, m = e & 63;
    int rp = ((n >> 3) - (m >> 3) + 7) * 15 + ((n & 7) - (m & 7) + 7);
    g_bias[e] = table[rp * 8 + h];
}

// fused: window-partition q -> half, and window-mean -> g_qg (single q read)
__global__ void __launch_bounds__(256) pack_qg_kernel(const float* __restrict__ q) {
    int w = blockIdx.x;                        // 0..2047
    int c = threadIdx.x;
    int b = w >> 10, hg = (w >> 5) & 31, wg = w & 31;
    const float* base = q + (((size_t)(b * 256 + hg * 8)) * 256 + wg * 8) * 256 + c;
    __half* dst = g_qwh + (size_t)w * 64 * 256 + c;
    float s = 0.f;
#pragma unroll
    for (int i = 0; i < 8; i++)
#pragma unroll
        for (int j = 0; j < 8; j++) {
            float v = base[(size_t)(i * 256 + j) * 256];
            s += v;
            dst[(size_t)(i * 8 + j) * 256] = __float2half(v);
        }
    g_qg[(size_t)w * 256 + c] = s * (1.0f / 64.0f);
}

// ---------------- sim = qg @ kg^T (fp32, cp.async 2-stage) ----------------
__global__ void __launch_bounds__(256) sim_kernel(const float* __restrict__ kg1,
                                                  const float* __restrict__ kg2,
                                                  const float* __restrict__ kg3) {
    __shared__ float buf[2][SIM_STAGE_F];
    __shared__ const float* browp[64];
    int b = blockIdx.z;
    int r0 = blockIdx.y * 64;
    int c0 = blockIdx.x * 64;
    int t = threadIdx.x;
    int ty = t >> 4, tx = t & 15;

    if (t < 64) {
        int m = c0 + t;
        const float* p;
        if (m < 1024)      p = kg1 + (size_t)(b * 1024 + m) * 256;
        else if (m < 1280) p = kg2 + (size_t)(b * 256 + m - 1024) * 256;
        else               p = kg3 + (size_t)(b * 64  + m - 1280) * 256;
        browp[t] = p;
    }
    __syncthreads();

    const float* abase = g_qg + (size_t)(b * NQ + r0) * 256;
    unsigned smem_u32 = (unsigned)__cvta_generic_to_shared(&buf[0][0]);

    auto load_stage = [&](int st, int kit) {
        int k0 = kit * 16;
        unsigned sb = smem_u32 + (unsigned)(st * SIM_STAGE_F) * 4u;
#pragma unroll
        for (int u = 0; u < 2; u++) {
            int c = t + u * 256;          // 0..511
            int reg = c >> 8;             // 0=A, 1=B
            int rc = c & 255;
            int row = rc >> 2, seg = (rc & 3) << 2;
            const float* g = (reg == 0) ? (abase + (size_t)row * 256 + k0 + seg)
                                        : (browp[row] + k0 + seg);
            unsigned dst = sb + (unsigned)((reg * 64 + row) * SLD + seg) * 4u;
            cpa16(dst, g);
        }
        cpa_commit();
    };

    float acc[4][4];
#pragma unroll
    for (int i = 0; i < 4; i++)
#pragma unroll
        for (int j = 0; j < 4; j++) acc[i][j] = 0.f;

    load_stage(0, 0);
#pragma unroll
    for (int k = 0; k < 16; k++) {
        cpa_wait0();
        __syncthreads();
        if (k + 1 < 16) load_stage((k + 1) & 1, k + 1);
        const float* As = buf[k & 1];
        const float* Bs = As + 64 * SLD;
#pragma unroll
        for (int kk = 0; kk < 16; kk++) {
            float a_[4], b_[4];
#pragma unroll
            for (int i = 0; i < 4; i++) a_[i] = As[(ty * 4 + i) * SLD + kk];
#pragma unroll
            for (int j = 0; j < 4; j++) b_[j] = Bs[(tx * 4 + j) * SLD + kk];
#pragma unroll
            for (int i = 0; i < 4; i++)
#pragma unroll
                for (int j = 0; j < 4; j++) acc[i][j] += a_[i] * b_[j];
        }
    }
#pragma unroll
    for (int i = 0; i < 4; i++)
#pragma unroll
        for (int j = 0; j < 4; j++)
            g_sim[(size_t)(b * NQ + r0 + ty * 4 + i) * NKW + c0 + tx * 4 + j] = acc[i][j];
}

// ---------------- top-32 per row: one warp per row, register-resident ----------------
__global__ void __launch_bounds__(128) topk_kernel() {
    int r = blockIdx.x * 4 + (threadIdx.x >> 5);   // 4 rows per block
    int lane = threadIdx.x & 31;
    const float* row = g_sim + (size_t)r * NKW;
    float v[42];
#pragma unroll
    for (int i = 0; i < 42; i++) v[i] = row[i * 32 + lane];
    unsigned long long used = 0ull;
    for (int it = 0; it < TOPK; it++) {
        float bv = -1e38f; int bidx = 0;
#pragma unroll
        for (int i = 0; i < 42; i++) {
            bool ok = !((used >> i) & 1ull);
            if (ok && v[i] > bv) { bv = v[i]; bidx = i; }
        }
        int gi = bidx * 32 + lane;
#pragma unroll
        for (int off = 16; off; off >>= 1) {
            float ov = __shfl_down_sync(FULLMASK, bv, off);
            int   oi = __shfl_down_sync(FULLMASK, gi, off);
            if (ov > bv || (ov == bv && oi < gi)) { bv = ov; gi = oi; }
        }
        gi = __shfl_sync(FULLMASK, gi, 0);
        if (lane == 0) g_top[r * TOPK + it] = gi;
        if ((gi & 31) == lane) used |= 1ull << (gi >> 5);
    }
}

// ---------------- greedy assignment: group-speculative (G=8), register bitmap ----------------
// lane l owns columns c with (c & 31) == l; bit index = c >> 5 (0..41).
// Per group of 8 rows: free flags from one used64 snapshot (8 pipelined shfls);
// intra-group conflicts fixed via local register compares after each broadcast.
__global__ void greedy_kernel() {
    extern __shared__ unsigned short tops[];       // NQ * TOPK (64 KB dynamic)
    int b = blockIdx.x;
    int lane = threadIdx.x;
    for (int i = lane; i < NQ * TOPK; i += 32) tops[i] = (unsigned short)g_top[b * NQ * TOPK + i];
    __syncwarp();

    unsigned long long used64 = 0ull;
    for (int n0 = 0; n0 < NQ; n0 += 8) {
        int cand[8];
        bool fr[8];
#pragma unroll
        for (int g = 0; g < 8; g++) cand[g] = (int)tops[(n0 + g) * TOPK + lane];
#pragma unroll
        for (int g = 0; g < 8; g++) {
            unsigned long long w = __shfl_sync(FULLMASK, used64, cand[g] & 31);
            fr[g] = !((w >> (cand[g] >> 5)) & 1ull);
        }
        int chosen[8];
#pragma unroll
        for (int g = 0; g < 8; g++) {
            unsigned bal = __ballot_sync(FULLMASK, fr[g]);
            int c;
            if (bal) {
                c = __shfl_sync(FULLMASK, cand[g], __ffs(bal) - 1);
            } else {
                const float* row = g_sim + ((size_t)b * NQ + n0 + g) * NKW;
                float bv = -1e38f; int bi = NKW;
#pragma unroll
                for (int i = 0; i < 42; i++) {
                    int col = i * 32 + lane;
                    bool ok = !((used64 >> i) & 1ull);
#pragma unroll
                    for (int j = 0; j < 8; j++)
                        if (j < g && col == chosen[j]) ok = false;
                    if (ok) {
                        float vv = row[col];
                        if (vv > bv) { bv = vv; bi = col; }
                    }
                }
#pragma unroll
                for (int off = 16; off; off >>= 1) {
                    float ov = __shfl_down_sync(FULLMASK, bv, off);
                    int   oi = __shfl_down_sync(FULLMASK, bi, off);
                    if (ov > bv || (ov == bv && oi < bi)) { bv = ov; bi = oi; }
                }
                c = __shfl_sync(FULLMASK, bi, 0);
            }
            chosen[g] = c;
            // local conflict fix for later rows in this group (no ballots)
#pragma unroll
            for (int h = 0; h < 8; h++)
                if (h > g && cand[h] == c) fr[h] = false;
        }
        // commit group to the distributed bitmap
#pragma unroll
        for (int g = 0; g < 8; g++)
            if ((chosen[g] & 31) == lane) used64 |= 1ull << (chosen[g] >> 5);
        if (lane == 0) {
#pragma unroll
            for (int g = 0; g < 8; g++) g_idx[b * NQ + n0 + g] = chosen[g];
        }
    }
}

// ---------------- gather assigned k windows -> half (float4 per thread) ----------------
__global__ void __launch_bounds__(256) pack_k_kernel(const float* __restrict__ k1,
                                                     const float* __restrict__ k2,
                                                     const float* __restrict__ k3) {
    size_t gid = (size_t)blockIdx.x * 256 + threadIdx.x;  // each handles 4 elems
    int c = (int)(gid & 63) << 2;
    int rest = (int)(gid >> 6);
    int n = rest & 63, w = rest >> 6;
    int b = w >> 10;
    int win = g_idx[w];
    const float* src;
    if (win < 1024)      src = k1 + ((size_t)(b * 1024 + win) * 64 + n) * 256 + c;
    else if (win < 1280) src = k2 + ((size_t)(b * 256 + win - 1024) * 64 + n) * 256 + c;
    else                 src = k3 + ((size_t)(b * 64 + win - 1280) * 64 + n) * 256 + c;
    float4 v = *(const float4*)src;
    __half h[4] = {__float2half(v.x), __float2half(v.y), __float2half(v.z), __float2half(v.w)};
    *(float2*)(g_kwh + gid * 4) = *(float2*)h;
}

// ---------------- GEMM v5: 4 warps, 64x64 warp tiles, cp.async 2-stage ----------------
// MODE 0: half out = (acc+bias)*scale   MODE 1: half out = acc+bias (dual-output capable)
// MODE 2: float out = resid + acc + bias
template<int MODE>
__global__ void __launch_bounds__(128, 2) gemm5_kernel(const __half* __restrict__ A,
                                                       const __half* __restrict__ W,
                                                       const float* __restrict__ bias,
                                                       const float* __restrict__ bias2,
                                                       const float* __restrict__ resid,
                                                       void* __restrict__ out,
                                                       void* __restrict__ out2,
                                                       float scale) {
    extern __shared__ __half sm[];
    int t = threadIdx.x;
    int wid = t >> 5, lane = t & 31;
    int wm = wid >> 1, wn = wid & 1;                    // 2x2 warps, each 64x64
    int m0 = blockIdx.y * BM;
    int n0 = blockIdx.x * BN;
    unsigned smem_u32 = (unsigned)__cvta_generic_to_shared(sm);

    const __half* Ag = A + (size_t)m0 * 256;
    const __half* Wg = W + (size_t)n0 * 256;

    auto load_stage = [&](int st, int kit) {
        int k0 = kit * BK;
        unsigned sa = smem_u32 + (unsigned)(st * STAGE_HALFS) * 2u;
        unsigned sb = sa + (unsigned)(128 * LDT) * 2u;
#pragma unroll
        for (int u = 0; u < 8; u++) {
            int c = t + u * 128;                        // 0..1023
            int row = c >> 3, seg = (c & 7) << 3;       // seg in halfs
            cpa16(sa + (unsigned)(row * LDT + seg) * 2u, Ag + (size_t)row * 256 + k0 + seg);
            cpa16(sb + (unsigned)(row * LDT + seg) * 2u, Wg + (size_t)row * 256 + k0 + seg);
        }
        cpa_commit();
    };

    wmma::fragment<wmma::accumulator, 16, 16, 16, float> acc[4][4];
#pragma unroll
    for (int i = 0; i < 4; i++)
#pragma unroll
        for (int j = 0; j < 4; j++) wmma::fill_fragment(acc[i][j], 0.f);

    load_stage(0, 0);
#pragma unroll
    for (int k = 0; k < NKIT; k++) {
        cpa_wait0();
        __syncthreads();
        if (k + 1 < NKIT) load_stage((k + 1) & 1, k + 1);

        const __half* As = sm + (size_t)(k & 1) * STAGE_HALFS;
        const __half* Bs = As + 128 * LDT;
#pragma unroll
        for (int kk = 0; kk < BK; kk += 16) {
            wmma::fragment<wmma::matrix_a, 16, 16, 16, __half, wmma::row_major> a[4];
#pragma unroll
            for (int i = 0; i < 4; i++)
                wmma::load_matrix_sync(a[i], As + (wm * 64 + i * 16) * LDT + kk, LDT);
#pragma unroll
            for (int j = 0; j < 4; j++) {
                wmma::fragment<wmma::matrix_b, 16, 16, 16, __half, wmma::col_major> b;
                wmma::load_matrix_sync(b, Bs + (wn * 64 + j * 16) * LDT + kk, LDT);
#pragma unroll
                for (int i = 0; i < 4; i++)
                    wmma::mma_sync(acc[i][j], a[i], b, acc[i][j]);
            }
        }
    }
    __syncthreads();   // stages now dead -> reuse for epilogue staging

    const float* biasE = bias;
    void* outE = out;
    int nsub = 0;
    if (MODE == 1 && bias2 != nullptr && n0 >= 256) { biasE = bias2; outE = out2; nsub = 256; }

    float* wstg = (float*)sm + wid * 320;               // 16x20 floats per warp
    int r = lane >> 1, cs = (lane & 1) << 3;
#pragma unroll
    for (int i = 0; i < 4; i++)
#pragma unroll
        for (int j = 0; j < 4; j++) {
            wmma::store_matrix_sync(wstg, acc[i][j], 20, wmma::mem_row_major);
            __syncwarp();
            int m = m0 + wm * 64 + i * 16 + r;
            int n = n0 + wn * 64 + j * 16 + cs;
            int nc = n - nsub;
            size_t off = (size_t)m * 256 + nc;
            float v[8];
#pragma unroll
            for (int c = 0; c < 8; c++) v[c] = wstg[r * 20 + cs + c] + biasE[nc + c];
            if (MODE == 2) {
                float4 r0 = *(const float4*)(resid + off);
                float4 r1 = *(const float4*)(resid + off + 4);
                float4 w0 = {r0.x + v[0], r0.y + v[1], r0.z + v[2], r0.w + v[3]};
                float4 w1 = {r1.x + v[4], r1.y + v[5], r1.z + v[6], r1.w + v[7]};
                float* op = (float*)outE + off;
                *(float4*)op = w0; *(float4*)(op + 4) = w1;
            } else {
                __half h[8];
#pragma unroll
                for (int c = 0; c < 8; c++)
                    h[c] = __float2half(MODE == 0 ? v[c] * scale : v[c]);
                *(float4*)((__half*)outE + off) = *(float4*)h;
            }
            __syncwarp();
        }
}

// ---------------- attention per (window, head), smem-staged ----------------
__global__ void __launch_bounds__(256) attn_kernel(const float* __restrict__ qin) {
    __shared__ __half qs[64 * 40], ks[64 * 40], vs[64 * 40];
    __shared__ float  Ssm[64 * 68];
    __shared__ __half Psm[64 * 72];

    int w = blockIdx.x >> 3;
    int head = blockIdx.x & 7;
    int t = threadIdx.x;
    int wid = t >> 5;

    const __half* qb = g_qh + (size_t)w * 64 * 256 + head * 32;
    const __half* kb = g_kh + (size_t)w * 64 * 256 + head * 32;
    const __half* vb = g_vh + (size_t)w * 64 * 256 + head * 32;

    {
        int row = t >> 2, seg = (t & 3) << 3;
        *(float4*)(qs + row * 40 + seg) = *(const float4*)(qb + (size_t)row * 256 + seg);
        *(float4*)(ks + row * 40 + seg) = *(const float4*)(kb + (size_t)row * 256 + seg);
        *(float4*)(vs + row * 40 + seg) = *(const float4*)(vb + (size_t)row * 256 + seg);
    }
    __syncthreads();

#pragma unroll
    for (int tt = 0; tt < 2; tt++) {
        int tile = wid + tt * 8;
        int tr = tile >> 2, tc = tile & 3;
        wmma::fragment<wmma::accumulator, 16, 16, 16, float> acc;
        wmma::fill_fragment(acc, 0.f);
#pragma unroll
        for (int kk = 0; kk < 32; kk += 16) {
            wmma::fragment<wmma::matrix_a, 16, 16, 16, __half, wmma::row_major> a;
            wmma::fragment<wmma::matrix_b, 16, 16, 16, __half, wmma::col_major> b;
            wmma::load_matrix_sync(a, qs + (tr * 16) * 40 + kk, 40);
            wmma::load_matrix_sync(b, ks + (tc * 16) * 40 + kk, 40);
            wmma::mma_sync(acc, a, b, acc);
        }
        wmma::store_matrix_sync(Ssm + tr * 16 * 68 + tc * 16, acc, 68, wmma::mem_row_major);
    }
    __syncthreads();

    {
        int r = t >> 2, sub = t & 3;
        const float* brow = g_bias + head * 4096 + r * 64 + sub * 16;
        float vals[16];
        float mx = -1e38f;
#pragma unroll
        for (int i = 0; i < 16; i++) {
            vals[i] = Ssm[r * 68 + sub * 16 + i] + brow[i];
            mx = fmaxf(mx, vals[i]);
        }
        mx = fmaxf(mx, __shfl_xor_sync(FULLMASK, mx, 1));
        mx = fmaxf(mx, __shfl_xor_sync(FULLMASK, mx, 2));
        float sum = 0.f;
#pragma unroll
        for (int i = 0; i < 16; i++) {
            vals[i] = __expf(vals[i] - mx);
            sum += vals[i];
        }
        sum += __shfl_xor_sync(FULLMASK, sum, 1);
        sum += __shfl_xor_sync(FULLMASK, sum, 2);
        float inv = 1.0f / sum;
#pragma unroll
        for (int i = 0; i < 16; i++)
            Psm[r * 72 + sub * 16 + i] = __float2half(vals[i] * inv);
    }
    __syncthreads();

    {
        int tr = wid >> 1, tc = wid & 1;
        wmma::fragment<wmma::accumulator, 16, 16, 16, float> acc;
        wmma::fill_fragment(acc, 0.f);
#pragma unroll
        for (int mm = 0; mm < 64; mm += 16) {
            wmma::fragment<wmma::matrix_a, 16, 16, 16, __half, wmma::row_major> a;
            wmma::fragment<wmma::matrix_b, 16, 16, 16, __half, wmma::row_major> b;
            wmma::load_matrix_sync(a, Psm + tr * 16 * 72 + mm, 72);
            wmma::load_matrix_sync(b, vs + mm * 40 + tc * 16, 40);
            wmma::mma_sync(acc, a, b, acc);
        }
        wmma::store_matrix_sync(Ssm + tr * 16 * 36 + tc * 16, acc, 36, wmma::mem_row_major);
    }
    __syncthreads();

    {
        int b = w >> 10, hg = (w >> 5) & 31, wg = w & 31;
#pragma unroll
        for (int e0 = 0; e0 < 8; e0++) {
            int e = t * 8 + e0;
            int n = e >> 5, d = e & 31;
            int i = n >> 3, j = n & 7;
            size_t pix = (size_t)(b * 256 + hg * 8 + i) * 256 + wg * 8 + j;
            size_t off = pix * 256 + head * 32 + d;
            g_x[off] = qin[off] + Ssm[n * 36 + d];
        }
    }
}

// ---------------- LayerNorm -> half ----------------
__global__ void __launch_bounds__(256) ln_kernel(const float* __restrict__ lg,
                                                 const float* __restrict__ lb) {
    int row = blockIdx.x * 8 + (threadIdx.x >> 5);
    int lane = threadIdx.x & 31;
    const float* xr = g_x + (size_t)row * 256;
    float4 v0 = *(const float4*)(xr + lane * 8);
    float4 v1 = *(const float4*)(xr + lane * 8 + 4);
    float s = v0.x + v0.y + v0.z + v0.w + v1.x + v1.y + v1.z + v1.w;
#pragma unroll
    for (int off = 16; off; off >>= 1) s += __shfl_xor_sync(FULLMASK, s, off);
    float mu = s * (1.0f / 256.0f);
    float vs = 0.f;
    float d0[8] = {v0.x - mu, v0.y - mu, v0.z - mu, v0.w - mu,
                   v1.x - mu, v1.y - mu, v1.z - mu, v1.w - mu};
#pragma unroll
    for (int i = 0; i < 8; i++) vs += d0[i] * d0[i];
#pragma unroll
    for (int off = 16; off; off >>= 1) vs += __shfl_xor_sync(FULLMASK, vs, off);
    float rstd = rsqrtf(vs * (1.0f / 256.0f) + 1e-5f);
    __half* o = g_ln + (size_t)row * 256 + lane * 8;
#pragma unroll
    for (int i = 0; i < 8; i++) {
        int c = lane * 8 + i;
        o[i] = __float2half(d0[i] * rstd * lg[c] + lb[c]);
    }
}

// ---------------- launch ----------------
extern "C" void kernel_launch(void* const* d_in, const int* in_sizes, int n_in,
                              void* d_out, int out_size) {
    const float* q   = (const float*)d_in[0];
    const float* k1  = (const float*)d_in[1];
    const float* k2  = (const float*)d_in[2];
    const float* k3  = (const float*)d_in[3];
    const float* kg1 = (const float*)d_in[4];
    const float* kg2 = (const float*)d_in[5];
    const float* kg3 = (const float*)d_in[6];
    const float* rbt = (const float*)d_in[7];
    const float* Wq  = (const float*)d_in[8];
    const float* bq  = (const float*)d_in[9];
    const float* Wk  = (const float*)d_in[10];
    const float* bk  = (const float*)d_in[11];
    const float* Wv  = (const float*)d_in[12];
    const float* bv  = (const float*)d_in[13];
    const float* lng = (const float*)d_in[14];
    const float* lnb = (const float*)d_in[15];
    const float* Wp  = (const float*)d_in[16];
    const float* bp  = (const float*)d_in[17];
    float* out = (float*)d_out;

    __half *dWq, *dWkv, *dWp, *dqwh, *dkwh, *dqh, *dkh, *dvh, *dln;
    float *dx;
    cudaGetSymbolAddress((void**)&dWq,  g_Wq);
    cudaGetSymbolAddress((void**)&dWkv, g_Wkv);
    cudaGetSymbolAddress((void**)&dWp,  g_Wp);
    cudaGetSymbolAddress((void**)&dqwh, g_qwh);
    cudaGetSymbolAddress((void**)&dkwh, g_kwh);
    cudaGetSymbolAddress((void**)&dqh,  g_qh);
    cudaGetSymbolAddress((void**)&dkh,  g_kh);
    cudaGetSymbolAddress((void**)&dvh,  g_vh);
    cudaGetSymbolAddress((void**)&dln,  g_ln);
    cudaGetSymbolAddress((void**)&dx,   g_x);

    cudaFuncSetAttribute(gemm5_kernel<0>, cudaFuncAttributeMaxDynamicSharedMemorySize, SMEM_GEMM);
    cudaFuncSetAttribute(gemm5_kernel<1>, cudaFuncAttributeMaxDynamicSharedMemorySize, SMEM_GEMM);
    cudaFuncSetAttribute(gemm5_kernel<2>, cudaFuncAttributeMaxDynamicSharedMemorySize, SMEM_GEMM);
    cudaFuncSetAttribute(greedy_kernel, cudaFuncAttributeMaxDynamicSharedMemorySize, SMEM_GREEDY);

    const float scale = 0.17677669529663687f;   // 32^-0.5

    // fork-join (proven-clean single extra stream + 2 events): latency-bound
    // greedy chain overlaps the throughput-bound weight-conv + q-projection.
    cudaStream_t s2;
    cudaEvent_t e1, e2;
    cudaStreamCreateWithFlags(&s2, cudaStreamNonBlocking);
    cudaEventCreateWithFlags(&e1, cudaEventDisableTiming);
    cudaEventCreateWithFlags(&e2, cudaEventDisableTiming);

    pack_qg_kernel<<<NWIN, 256>>>(q);                              // 1
    sim_kernel<<<dim3(21, 16, 2), 256>>>(kg1, kg2, kg3);           // 2
    topk_kernel<<<NWIN / 4, 128>>>();                              // 3
    cudaEventRecord(e1, 0);

    cudaStreamWaitEvent(s2, e1, 0);
    greedy_kernel<<<2, 32, SMEM_GREEDY, s2>>>();                   // 4 <- ncu capture slot
    pack_k_kernel<<<MROWS * 64 / 256, 256, 0, s2>>>(k1, k2, k3);   // 5
    cudaEventRecord(e2, s2);

    conv_w_kernel<<<1024, 256>>>(Wq, Wk, Wv, Wp);                  // 6
    bias_kernel<<<128, 256>>>(rbt);                                // 7
    gemm5_kernel<0><<<dim3(2, 1024), 128, SMEM_GEMM>>>(dqwh, dWq, bq, nullptr, nullptr,
                                                       dqh, nullptr, scale);   // 8

    cudaStreamWaitEvent(0, e2, 0);
    gemm5_kernel<1><<<dim3(4, 1024), 128, SMEM_GEMM>>>(dkwh, dWkv, bk, bv, nullptr,
                                                       dkh, dvh, 0.f);

    attn_kernel<<<NWIN * 8, 256>>>(q);
    ln_kernel<<<MROWS / 8, 256>>>(lng, lnb);
    gemm5_kernel<2><<<dim3(2, 1024), 128, SMEM_GEMM>>>(dln, dWp, bp, nullptr, dx,
                                                       out, nullptr, 0.f);
}